// round 6
// baseline (speedup 1.0000x reference)
#include <cuda_runtime.h>
#include <cuda_bf16.h>
#include <cstdint>

#define NNODES 50000
#define HID    128
#define MAXD   16
#define NGRAPH 50
#define NCLS   10
#define GRUH   32
#define MAXB   3400

// ---------------- scratch ----------------
__device__ __nv_bfloat16 g_Pb [(size_t)NNODES * 512]; // feature@WihT, bf16, phys-permuted cols
__device__ float g_hT [(size_t)NNODES * HID];
__device__ float g_h1 [(size_t)NNODES * HID];
__device__ float g_agg[(size_t)NNODES * HID];
__device__ float g_h2 [(size_t)NNODES * HID];
__device__ float g_o32[(size_t)NNODES * GRUH];
__device__ float g_WihTp[HID * 512];         // [k][p] permuted
__device__ uint4 g_Wfrag4[256 * 32];         // Whh fragments, E/O fused per uint4
__device__ float4 g_biasF[HID];              // (bi,bf,bg,bo)
__device__ float4 g_Wt3 [HID * GRUH];        // GRU
// degree bucketing
__device__ int g_order[NNODES];
__device__ int g_batch_start[MAXB];
__device__ int g_batch_info[MAXB];           // (deg<<8)|cnt
__device__ int g_nbatch;

// ---------------- helpers ----------------
__device__ __forceinline__ float sigf(float x) {
    x = fminf(fmaxf(x, -30.f), 30.f);
    return __fdividef(1.f, 1.f + __expf(-x));
}
__device__ __forceinline__ float tanh_(float x) {
    x = fminf(fmaxf(x, -15.f), 15.f);
    float e = __expf(-2.f * x);
    return __fdividef(1.f - e, 1.f + e);
}
__device__ __forceinline__ float tanhap(float x) {
    float y; asm("tanh.approx.f32 %0, %1;" : "=f"(y) : "f"(x)); return y;
}
__device__ __forceinline__ float sigt(float x) { return fmaf(tanhap(x * 0.5f), 0.5f, 0.5f); }
__device__ __forceinline__ unsigned bf16u(float x) {
    __nv_bfloat16 b = __float2bfloat16(x);
    return (unsigned)*reinterpret_cast<unsigned short*>(&b);
}
__device__ __forceinline__ float blo(unsigned v) { return __uint_as_float(v << 16); }
__device__ __forceinline__ float bhi(unsigned v) { return __uint_as_float(v & 0xFFFF0000u); }

// phys col p -> logical LSTM row (gamma*128+j)
__host__ __device__ __forceinline__ int phys2row(int p) {
    int pb = p >> 4, rem = p & 15;
    int gamma, aa;
    if (rem < 8) { aa = rem >> 1; gamma = (rem & 1) ? 1 : 0; }
    else         { aa = (rem - 8) >> 1; gamma = (rem & 1) ? 3 : 2; }
    return gamma * HID + pb * 4 + aa;
}

__device__ __forceinline__ void mma16816(float* d, const unsigned* a, unsigned b0, unsigned b1) {
    asm volatile(
        "mma.sync.aligned.m16n8k16.row.col.f32.bf16.bf16.f32 "
        "{%0,%1,%2,%3}, {%4,%5,%6,%7}, {%8,%9}, {%0,%1,%2,%3};"
        : "+f"(d[0]), "+f"(d[1]), "+f"(d[2]), "+f"(d[3])
        : "r"(a[0]), "r"(a[1]), "r"(a[2]), "r"(a[3]), "r"(b0), "r"(b1));
}

// ---------------- prep ----------------
__global__ void prep_kernel(const float* __restrict__ Wih,
                            const float* __restrict__ Whh,
                            const float* __restrict__ bih,
                            const float* __restrict__ bhh,
                            const float* __restrict__ Wgru) {
    int idx = blockIdx.x * blockDim.x + threadIdx.x;
    if (idx < HID * 512) {
        int k = idx >> 9, p = idx & 511;
        g_WihTp[idx] = Wih[phys2row(p) * HID + k];
    }
    if (idx < 512 * 32) {            // per-tile uint2 fragments, repacked E/O-fused
        int t_id = idx >> 5, lane = idx & 31;
        int kt = t_id >> 6, ntg = t_id & 63;
        int p = ntg * 8 + (lane >> 2);
        int wrow = phys2row(p);
        int k0 = kt * 16 + (lane & 3) * 2;
        const float* wr = Whh + (size_t)wrow * HID;
        uint2 v;
        v.x = bf16u(wr[k0])     | (bf16u(wr[k0 + 1]) << 16);
        v.y = bf16u(wr[k0 + 8]) | (bf16u(wr[k0 + 9]) << 16);
        int chunk = ntg >> 4, nt = ntg & 15;
        int pp = nt >> 1, isO = nt & 1;
        int dst = (((kt << 5) | (chunk << 3) | pp) * 32 + lane) * 2 + isO;
        ((uint2*)g_Wfrag4)[dst] = v;
    }
    if (idx < HID) {
        g_biasF[idx] = make_float4(bih[idx] + bhh[idx],
                                   bih[HID + idx] + bhh[HID + idx],
                                   bih[2 * HID + idx] + bhh[2 * HID + idx],
                                   bih[3 * HID + idx] + bhh[3 * HID + idx]);
    }
    if (idx < HID * GRUH) {
        int k = idx >> 5, l = idx & 31;
        g_Wt3[idx] = make_float4(Wgru[(0 * GRUH + l) * HID + k],
                                 Wgru[(1 * GRUH + l) * HID + k],
                                 Wgru[(2 * GRUH + l) * HID + k], 0.f);
    }
}

// -------- single-block deterministic bucketing (desc degree, batches of 16) --------
__global__ void k_bucket(const int* __restrict__ deg) {
    __shared__ unsigned short cnts[512][16];
    __shared__ int btot[16], binbase[16];
    int tid = threadIdx.x;
    int lc[16];
#pragma unroll
    for (int b = 0; b < 16; ++b) lc[b] = 0;
    for (int i = tid; i < NNODES; i += 512) lc[deg[i] - 1]++;
#pragma unroll
    for (int b = 0; b < 16; ++b) cnts[tid][b] = (unsigned short)lc[b];
    __syncthreads();
    if (tid < 16) {
        int run = 0;
        for (int j = 0; j < 512; ++j) {
            int v = cnts[j][tid];
            cnts[j][tid] = (unsigned short)run;
            run += v;
        }
        btot[tid] = run;
    }
    __syncthreads();
    if (tid == 0) {
        int off = 0;
        for (int b = 0; b < 16; ++b) { binbase[b] = off; off += btot[b]; }
        int bo = 0;
        for (int b = 15; b >= 0; --b) {
            for (int j = 0; j < btot[b]; j += 16, ++bo) {
                g_batch_start[bo] = binbase[b] + j;
                g_batch_info[bo]  = ((b + 1) << 8) | min(16, btot[b] - j);
            }
        }
        g_nbatch = bo;
    }
    __syncthreads();
#pragma unroll
    for (int b = 0; b < 16; ++b) lc[b] = binbase[b] + cnts[tid][b];
    for (int i = tid; i < NNODES; i += 512) {
        int d = deg[i] - 1;
        g_order[lc[d]++] = i;
    }
}

// ---------------- generic K=128 GEMM ----------------
__global__ void gemm128(const float* __restrict__ A,  const float* __restrict__ W,
                        const float* __restrict__ A2, const float* __restrict__ W2,
                        const float* __restrict__ bias, void* __restrict__ C,
                        int M, int N, int outmode) {
    __shared__ float Asm[32][68];
    __shared__ float Wsm[32][64];
    int tid = threadIdx.x;
    int tx = tid & 15, ty = tid >> 4;
    int r0 = blockIdx.x * 64, c0 = blockIdx.y * 64;

    float acc[4][4];
#pragma unroll
    for (int i = 0; i < 4; i++)
#pragma unroll
        for (int j = 0; j < 4; j++) acc[i][j] = 0.f;

    int npass = (A2 != nullptr) ? 2 : 1;
    for (int p = 0; p < npass; ++p) {
        const float* Ap = p ? A2 : A;
        const float* Wp = p ? W2 : W;
        for (int kk = 0; kk < 128; kk += 32) {
            __syncthreads();
            {
                int k = tid & 31, r = tid >> 5;
#pragma unroll
                for (int pp = 0; pp < 8; ++pp) {
                    int row = r0 + r + pp * 8;
                    row = min(row, M - 1);
                    Asm[k][r + pp * 8] = Ap[(size_t)row * 128 + kk + k];
                }
            }
            {
                int c = tid & 63, kq = tid >> 6;
#pragma unroll
                for (int pp = 0; pp < 8; ++pp)
                    Wsm[kq + pp * 4][c] = Wp[(size_t)(kk + kq + pp * 4) * N + c0 + c];
            }
            __syncthreads();
#pragma unroll
            for (int k = 0; k < 32; ++k) {
                float4 a4 = *(const float4*)&Asm[k][ty * 4];
                float4 w4 = *(const float4*)&Wsm[k][tx * 4];
                float ar[4] = {a4.x, a4.y, a4.z, a4.w};
                float wc[4] = {w4.x, w4.y, w4.z, w4.w};
#pragma unroll
                for (int i = 0; i < 4; i++)
#pragma unroll
                    for (int j = 0; j < 4; j++)
                        acc[i][j] = fmaf(ar[i], wc[j], acc[i][j]);
            }
        }
    }
#pragma unroll
    for (int i = 0; i < 4; i++) {
        int row = r0 + ty * 4 + i;
        if (row < M) {
#pragma unroll
            for (int j = 0; j < 4; j++) {
                int col = c0 + tx * 4 + j;
                float v = acc[i][j] + (bias ? bias[col] : 0.f);
                if (outmode == 1) v = fmaxf(v, 0.f);
                if (outmode == 2)
                    ((__nv_bfloat16*)C)[(size_t)row * N + col] = __float2bfloat16(v);
                else
                    ((float*)C)[(size_t)row * N + col] = v;
            }
        }
    }
}

// ------- mma.sync LSTM: 4-warp groups, 4 groups/CTA, double-buffered h -------
#define LGROUPS 4
#define HSTRIDE 136
#define SM_WF    0                                   // 131072
#define SM_BIAS  131072                              // 2048
#define SM_HSTG  133120                              // 4*2*16*136*2 = 34816
#define SM_NID   (SM_HSTG + 34816)                   // 256
#define SM_USM   (SM_NID + 256)                      // 4*16*16*4 = 4096
#define SM_TOTAL (SM_USM + 4096)

__global__ __launch_bounds__(512, 1)
void lstm_mma(const int* __restrict__ nbr) {
    extern __shared__ char smr[];
    uint4*  wf  = (uint4*)(smr + SM_WF);
    float4* bsm = (float4*)(smr + SM_BIAS);
    __nv_bfloat16* hstg = (__nv_bfloat16*)(smr + SM_HSTG);
    int* nidA = (int*)(smr + SM_NID);
    int* usmA = (int*)(smr + SM_USM);

    int tid = threadIdx.x, wid = tid >> 5, lane = tid & 31;
    for (int i = tid; i < 256 * 32; i += 512) wf[i] = g_Wfrag4[i];
    if (tid < HID) bsm[tid] = g_biasF[tid];
    __syncthreads();

    int grp = wid >> 2, chunk = wid & 3;
    __nv_bfloat16* hs0 = hstg + grp * 2 * 16 * HSTRIDE;
    __nv_bfloat16* hs1 = hs0 + 16 * HSTRIDE;
    int* mynid = nidA + grp * 16;
    int* usm   = usmA + grp * 16 * MAXD;
    int r0 = lane >> 2, q = lane & 3;
    int barid = grp + 1;
    int nb = g_nbatch;
    const unsigned* PB = (const unsigned*)g_Pb;   // row stride 256 words

    for (int b = blockIdx.x * LGROUPS + grp; b < nb; b += gridDim.x * LGROUPS) {
        asm volatile("bar.sync %0, %1;" :: "r"(barid), "r"(128) : "memory"); // prev batch done
        int start = g_batch_start[b];
        int info  = g_batch_info[b];
        int dmax = info >> 8, cnt = info & 255;
        if (chunk == 0 && lane < 16) {
            int nid = g_order[start + min(lane, cnt - 1)];
            mynid[lane] = nid;
            const int4* src = (const int4*)(nbr + nid * MAXD);
            int4* dst = (int4*)(usm + lane * MAXD);
            dst[0] = src[0]; dst[1] = src[1]; dst[2] = src[2]; dst[3] = src[3];
        }
        asm volatile("bar.sync %0, %1;" :: "r"(barid), "r"(128) : "memory"); // ids published

        float cst[16];
#pragma unroll
        for (int i = 0; i < 16; ++i) cst[i] = 0.f;

        // prefetch row-lo P for t=0
        unsigned pnl[16];
        {
            const unsigned* L = PB + (size_t)usm[r0 * MAXD] * 256;
#pragma unroll
            for (int nt = 0; nt < 16; ++nt) pnl[nt] = L[chunk * 64 + nt * 4 + q];
        }

        for (int t = 0; t < dmax; ++t) {
            // single bar: prev step's h writes visible AND prev reads complete
            asm volatile("bar.sync %0, %1;" :: "r"(barid), "r"(128) : "memory");
            const __nv_bfloat16* hsR = (t & 1) ? hs0 : hs1;
            __nv_bfloat16*       hsW = (t & 1) ? hs1 : hs0;

            unsigned a[8][4];
            if (t > 0) {
#pragma unroll
                for (int kt = 0; kt < 8; ++kt) {
                    const __nv_bfloat16* hb = hsR + kt * 16 + q * 2;
                    a[kt][0] = *(const unsigned*)(hb + r0 * HSTRIDE);
                    a[kt][1] = *(const unsigned*)(hb + (r0 + 8) * HSTRIDE);
                    a[kt][2] = *(const unsigned*)(hb + r0 * HSTRIDE + 8);
                    a[kt][3] = *(const unsigned*)(hb + (r0 + 8) * HSTRIDE + 8);
                }
            }
            unsigned pcl[16];
#pragma unroll
            for (int nt = 0; nt < 16; ++nt) pcl[nt] = pnl[nt];
            // row-hi P for this step (covered by the MMA section below)
            unsigned pch[16];
            {
                const unsigned* H = PB + (size_t)usm[(r0 + 8) * MAXD + t] * 256;
#pragma unroll
                for (int nt = 0; nt < 16; ++nt) pch[nt] = H[chunk * 64 + nt * 4 + q];
            }
            // row-lo P for next step
            if (t + 1 < dmax) {
                const unsigned* L = PB + (size_t)usm[r0 * MAXD + t + 1] * 256;
#pragma unroll
                for (int nt = 0; nt < 16; ++nt) pnl[nt] = L[chunk * 64 + nt * 4 + q];
            }

            bool last = (t == dmax - 1);
#pragma unroll
            for (int p = 0; p < 8; ++p) {
                float aE[4] = {0.f, 0.f, 0.f, 0.f};
                float aO[4] = {0.f, 0.f, 0.f, 0.f};
                if (t > 0) {
#pragma unroll
                    for (int kt = 0; kt < 8; ++kt) {
                        uint4 bb = wf[((kt << 5) | (chunk << 3) | p) * 32 + lane];
                        mma16816(aE, a[kt], bb.x, bb.y);
                        mma16816(aO, a[kt], bb.z, bb.w);
                    }
                }
                int J = chunk * 32 + p * 4 + q;
                float4 bs = bsm[J];
                {   // node row r0
                    float gi = aE[0] + blo(pcl[2 * p])     + bs.x;
                    float gf = aE[1] + bhi(pcl[2 * p])     + bs.y;
                    float gg = aO[0] + blo(pcl[2 * p + 1]) + bs.z;
                    float go = aO[1] + bhi(pcl[2 * p + 1]) + bs.w;
                    float cn = sigt(gf) * cst[2 * p] + sigt(gi) * tanhap(gg);
                    cst[2 * p] = cn;
                    float h = sigt(go) * tanhap(cn);
                    if (!last) hsW[r0 * HSTRIDE + J] = __float2bfloat16(h);
                    else if (r0 < cnt) g_hT[(size_t)mynid[r0] * HID + J] = h;
                }
                {   // node row r0+8
                    float gi = aE[2] + blo(pch[2 * p])     + bs.x;
                    float gf = aE[3] + bhi(pch[2 * p])     + bs.y;
                    float gg = aO[2] + blo(pch[2 * p + 1]) + bs.z;
                    float go = aO[3] + bhi(pch[2 * p + 1]) + bs.w;
                    float cn = sigt(gf) * cst[2 * p + 1] + sigt(gi) * tanhap(gg);
                    cst[2 * p + 1] = cn;
                    float h = sigt(go) * tanhap(cn);
                    if (!last) hsW[(r0 + 8) * HSTRIDE + J] = __float2bfloat16(h);
                    else if (r0 + 8 < cnt) g_hT[(size_t)mynid[r0 + 8] * HID + J] = h;
                }
            }
        }
    }
}

// ---------------- GraphConv aggregate ----------------
__global__ void agg_kernel(const int* __restrict__ nbr, const int* __restrict__ deg) {
    int wid  = (blockIdx.x * blockDim.x + threadIdx.x) >> 5;
    int lane = threadIdx.x & 31;
    if (wid >= NNODES) return;
    int d = deg[wid];
    const int* nb = nbr + wid * MAXD;
    float4 acc = {0.f, 0.f, 0.f, 0.f};
    for (int t = 0; t < d; ++t) {
        int u = nb[t];
        float nu = rsqrtf((float)max(deg[u], 1));
        float4 v = *(const float4*)(g_h1 + (size_t)u * 128 + lane * 4);
        acc.x = fmaf(v.x, nu, acc.x); acc.y = fmaf(v.y, nu, acc.y);
        acc.z = fmaf(v.z, nu, acc.z); acc.w = fmaf(v.w, nu, acc.w);
    }
    float nn = rsqrtf((float)max(d, 1));
    float4 o = {acc.x * nn, acc.y * nn, acc.z * nn, acc.w * nn};
    *(float4*)(g_agg + (size_t)wid * 128 + lane * 4) = o;
}

// ---------------- GRU ----------------
__global__ void gru_kernel(const float* __restrict__ bih, const float* __restrict__ bhh) {
    extern __shared__ char sm[];
    float4* Wt   = (float4*)sm;
    float*  hrow = (float*)(sm + 65536);
    int tid = threadIdx.x;
    for (int i = tid; i < HID * GRUH; i += blockDim.x) Wt[i] = g_Wt3[i];
    __syncthreads();

    int w = tid >> 5, lane = tid & 31;
    float br = bih[lane], bz = bih[32 + lane], bn = bih[64 + lane];
    float cr = bhh[lane], cz = bhh[32 + lane], cnb = bhh[64 + lane];
    float* hr = hrow + w * 128;
    int nwarp = gridDim.x * 8;
    for (int node = blockIdx.x * 8 + w; node < NNODES; node += nwarp) {
        const float* h2 = g_h2 + (size_t)node * 128;
        *(float4*)(hr + lane * 4) = *(const float4*)(h2 + lane * 4);
        __syncwarp();
        float ar = 0.f, az = 0.f, an = 0.f;
#pragma unroll 8
        for (int k = 0; k < 128; ++k) {
            float hk = hr[k];
            float4 wv = Wt[k * 32 + lane];
            ar = fmaf(hk, wv.x, ar);
            az = fmaf(hk, wv.y, az);
            an = fmaf(hk, wv.z, an);
        }
        __syncwarp();
        float r   = sigf(ar + br + cr);
        float z   = sigf(az + bz + cz);
        float nst = tanh_(an + bn + r * cnb);
        g_o32[(size_t)node * 32 + lane] = (1.f - z) * nst;
    }
}

// ---------------- mean pool + classifier ----------------
__global__ void pool_kernel(const int* __restrict__ gid,
                            const float* __restrict__ Wc,
                            const float* __restrict__ bc,
                            float* __restrict__ out) {
    __shared__ float s[8][32];
    __shared__ int   scnt[8];
    __shared__ float hg[32];
    int g = blockIdx.x;
    int tid = threadIdx.x, lane = tid & 31, slot = tid >> 5;
    float acc = 0.f;
    int cnt = 0;
    for (int i = slot; i < NNODES; i += 8) {
        if (gid[i] == g) {
            acc += g_o32[(size_t)i * 32 + lane];
            cnt++;
        }
    }
    s[slot][lane] = acc;
    if (lane == 0) scnt[slot] = cnt;
    __syncthreads();
    if (tid < 32) {
        float sum = 0.f; int tot = 0;
#pragma unroll
        for (int j = 0; j < 8; ++j) { sum += s[j][tid]; tot += scnt[j]; }
        hg[tid] = sum / (float)tot;
    }
    __syncthreads();
    if (tid < NCLS) {
        float o = bc[tid];
#pragma unroll
        for (int k = 0; k < 32; ++k) o = fmaf(hg[k], Wc[k * NCLS + tid], o);
        out[g * NCLS + tid] = o;
    }
}

// ---------------- launch ----------------
extern "C" void kernel_launch(void* const* d_in, const int* in_sizes, int n_in,
                              void* d_out, int out_size) {
    const float* feature = (const float*)d_in[0];
    const int*   nbr     = (const int*)  d_in[1];
    const int*   deg     = (const int*)  d_in[2];
    const int*   gid     = (const int*)  d_in[3];
    const float* lWih    = (const float*)d_in[4];
    const float* lWhh    = (const float*)d_in[5];
    const float* lbih    = (const float*)d_in[6];
    const float* lbhh    = (const float*)d_in[7];
    const float* Wself   = (const float*)d_in[8];
    const float* Wneigh  = (const float*)d_in[9];
    const float* bsage   = (const float*)d_in[10];
    const float* Wgc     = (const float*)d_in[11];
    const float* bgc     = (const float*)d_in[12];
    const float* Wgru    = (const float*)d_in[13];
    const float* bihg    = (const float*)d_in[14];
    const float* bhhg    = (const float*)d_in[15];
    const float* Wcls    = (const float*)d_in[16];
    const float* bcls    = (const float*)d_in[17];
    float* out = (float*)d_out;

    cudaFuncSetAttribute(lstm_mma, cudaFuncAttributeMaxDynamicSharedMemorySize, SM_TOTAL);
    cudaFuncSetAttribute(gru_kernel, cudaFuncAttributeMaxDynamicSharedMemorySize, 69632 + 256);

    void *pPb, *pWihTp, *phT, *ph1, *pagg, *ph2;
    cudaGetSymbolAddress(&pPb,    g_Pb);
    cudaGetSymbolAddress(&pWihTp, g_WihTp);
    cudaGetSymbolAddress(&phT,    g_hT);
    cudaGetSymbolAddress(&ph1,    g_h1);
    cudaGetSymbolAddress(&pagg,   g_agg);
    cudaGetSymbolAddress(&ph2,    g_h2);

    // 1. pack weights
    prep_kernel<<<256, 256>>>(lWih, lWhh, lbih, lbhh, Wgru);
    // 2. P = feature @ WihT_perm -> bf16 permuted [N,512] (bias added in lstm epilogue)
    {
        dim3 grid((NNODES + 63) / 64, 512 / 64);
        gemm128<<<grid, 256>>>(feature, (const float*)pWihTp, nullptr, nullptr,
                               nullptr, pPb, NNODES, 512, 2);
    }
    // 3. deterministic bucketing
    k_bucket<<<1, 512>>>(deg);
    // 4. LSTM (launch #4 -> profiled slot)
    lstm_mma<<<152, 512, SM_TOTAL>>>(nbr);
    // 5. h1 = relu(feature@W_self + hT@W_neigh + b_sage)
    {
        dim3 grid((NNODES + 63) / 64, 128 / 64);
        gemm128<<<grid, 256>>>(feature, Wself, (const float*)phT, Wneigh,
                               bsage, ph1, NNODES, 128, 1);
    }
    // 6. GraphConv aggregate
    agg_kernel<<<(NNODES * 32 + 255) / 256, 256>>>(nbr, deg);
    // 7. h2 = relu(agg @ W_gc + b_gc)
    {
        dim3 grid((NNODES + 63) / 64, 128 / 64);
        gemm128<<<grid, 256>>>((const float*)pagg, Wgc, nullptr, nullptr,
                               bgc, ph2, NNODES, 128, 1);
    }
    // 8. GRU
    gru_kernel<<<304, 256, 69632 + 256>>>(bihg, bhhg);
    // 9. mean pool + classifier
    pool_kernel<<<NGRAPH, 256>>>(gid, Wcls, bcls, out);
}

// round 7
// speedup vs baseline: 1.2289x; 1.2289x over previous
#include <cuda_runtime.h>
#include <cuda_bf16.h>
#include <cstdint>

#define NNODES 50000
#define HID    128
#define MAXD   16
#define NGRAPH 50
#define NCLS   10
#define GRUH   32
#define MAXB   3400

// ---------------- scratch ----------------
__device__ __nv_bfloat16 g_Pb [(size_t)NNODES * 512]; // feature@WihT, bf16, phys-permuted cols
__device__ __nv_bfloat16 g_featB[(size_t)NNODES * HID];
__device__ __nv_bfloat16 g_hTb [(size_t)NNODES * HID];
__device__ __nv_bfloat16 g_h1b [(size_t)NNODES * HID];
__device__ __nv_bfloat16 g_aggB[(size_t)NNODES * HID];
__device__ float g_h2 [(size_t)NNODES * HID];
__device__ float g_o32[(size_t)NNODES * GRUH];
__device__ uint2 g_WfP[16384];               // Wih fragments (N=512, permuted cols)
__device__ uint2 g_WfSelf[4096];
__device__ uint2 g_WfNeigh[4096];
__device__ uint2 g_WfGc[4096];
__device__ uint4 g_Wfrag4[256 * 32];         // lstm Whh fragments, E/O fused
__device__ float4 g_biasF[HID];              // (bi,bf,bg,bo)
__device__ float4 g_Wt3 [HID * GRUH];        // GRU
// degree bucketing
__device__ int g_order[NNODES];
__device__ int g_batch_start[MAXB];
__device__ int g_batch_info[MAXB];           // (deg<<8)|cnt
__device__ int g_nbatch;

// ---------------- helpers ----------------
__device__ __forceinline__ float sigf(float x) {
    x = fminf(fmaxf(x, -30.f), 30.f);
    return __fdividef(1.f, 1.f + __expf(-x));
}
__device__ __forceinline__ float tanh_(float x) {
    x = fminf(fmaxf(x, -15.f), 15.f);
    float e = __expf(-2.f * x);
    return __fdividef(1.f - e, 1.f + e);
}
__device__ __forceinline__ float tanhap(float x) {
    float y; asm("tanh.approx.f32 %0, %1;" : "=f"(y) : "f"(x)); return y;
}
__device__ __forceinline__ float sigt(float x) { return fmaf(tanhap(x * 0.5f), 0.5f, 0.5f); }
__device__ __forceinline__ unsigned bf16u(float x) {
    __nv_bfloat16 b = __float2bfloat16(x);
    return (unsigned)*reinterpret_cast<unsigned short*>(&b);
}
__device__ __forceinline__ float blo(unsigned v) { return __uint_as_float(v << 16); }
__device__ __forceinline__ float bhi(unsigned v) { return __uint_as_float(v & 0xFFFF0000u); }

__host__ __device__ __forceinline__ int phys2row(int p) {
    int pb = p >> 4, rem = p & 15;
    int gamma, aa;
    if (rem < 8) { aa = rem >> 1; gamma = (rem & 1) ? 1 : 0; }
    else         { aa = (rem - 8) >> 1; gamma = (rem & 1) ? 3 : 2; }
    return gamma * HID + pb * 4 + aa;
}

__device__ __forceinline__ void mma16816(float* d, const unsigned* a, unsigned b0, unsigned b1) {
    asm volatile(
        "mma.sync.aligned.m16n8k16.row.col.f32.bf16.bf16.f32 "
        "{%0,%1,%2,%3}, {%4,%5,%6,%7}, {%8,%9}, {%0,%1,%2,%3};"
        : "+f"(d[0]), "+f"(d[1]), "+f"(d[2]), "+f"(d[3])
        : "r"(a[0]), "r"(a[1]), "r"(a[2]), "r"(a[3]), "r"(b0), "r"(b1));
}

// ---------------- prep: all weight packing ----------------
__global__ void prep_kernel(const float* __restrict__ Wih,
                            const float* __restrict__ Whh,
                            const float* __restrict__ bih,
                            const float* __restrict__ bhh,
                            const float* __restrict__ Wself,
                            const float* __restrict__ Wneigh,
                            const float* __restrict__ Wgc,
                            const float* __restrict__ Wgru) {
    int idx = blockIdx.x * blockDim.x + threadIdx.x;
    if (idx < 16384) {                 // P fragments: Wt[k][p] = Wih[phys2row(p)][k]
        int l = idx & 31, t = idx >> 5;
        int kt = t >> 6, g = t & 63;
        int n = g * 8 + (l >> 2);
        int k0 = kt * 16 + (l & 3) * 2;
        int r = phys2row(n) * HID;
        uint2 v;
        v.x = bf16u(Wih[r + k0])     | (bf16u(Wih[r + k0 + 1]) << 16);
        v.y = bf16u(Wih[r + k0 + 8]) | (bf16u(Wih[r + k0 + 9]) << 16);
        g_WfP[idx] = v;
    }
    if (idx < 4096) {                  // Wself/Wneigh/Wgc fragments: Wt[k][n] = W[k*128+n]
        int l = idx & 31, t = idx >> 5;
        int kt = t >> 4, g = t & 15;
        int n = g * 8 + (l >> 2);
        int k0 = kt * 16 + (l & 3) * 2;
        uint2 v;
        v.x = bf16u(Wself[k0 * HID + n])       | (bf16u(Wself[(k0 + 1) * HID + n]) << 16);
        v.y = bf16u(Wself[(k0 + 8) * HID + n]) | (bf16u(Wself[(k0 + 9) * HID + n]) << 16);
        g_WfSelf[idx] = v;
        v.x = bf16u(Wneigh[k0 * HID + n])       | (bf16u(Wneigh[(k0 + 1) * HID + n]) << 16);
        v.y = bf16u(Wneigh[(k0 + 8) * HID + n]) | (bf16u(Wneigh[(k0 + 9) * HID + n]) << 16);
        g_WfNeigh[idx] = v;
        v.x = bf16u(Wgc[k0 * HID + n])       | (bf16u(Wgc[(k0 + 1) * HID + n]) << 16);
        v.y = bf16u(Wgc[(k0 + 8) * HID + n]) | (bf16u(Wgc[(k0 + 9) * HID + n]) << 16);
        g_WfGc[idx] = v;
    }
    if (idx < 512 * 32) {              // lstm Whh fragments, E/O fused
        int t_id = idx >> 5, lane = idx & 31;
        int kt = t_id >> 6, ntg = t_id & 63;
        int p = ntg * 8 + (lane >> 2);
        int wrow = phys2row(p);
        int k0 = kt * 16 + (lane & 3) * 2;
        const float* wr = Whh + (size_t)wrow * HID;
        uint2 v;
        v.x = bf16u(wr[k0])     | (bf16u(wr[k0 + 1]) << 16);
        v.y = bf16u(wr[k0 + 8]) | (bf16u(wr[k0 + 9]) << 16);
        int chunk = ntg >> 4, nt = ntg & 15;
        int pp = nt >> 1, isO = nt & 1;
        int dst = (((kt << 5) | (chunk << 3) | pp) * 32 + lane) * 2 + isO;
        ((uint2*)g_Wfrag4)[dst] = v;
    }
    if (idx < HID) {
        g_biasF[idx] = make_float4(bih[idx] + bhh[idx],
                                   bih[HID + idx] + bhh[HID + idx],
                                   bih[2 * HID + idx] + bhh[2 * HID + idx],
                                   bih[3 * HID + idx] + bhh[3 * HID + idx]);
    }
    if (idx < HID * GRUH) {
        int k = idx >> 5, l = idx & 31;
        g_Wt3[idx] = make_float4(Wgru[(0 * GRUH + l) * HID + k],
                                 Wgru[(1 * GRUH + l) * HID + k],
                                 Wgru[(2 * GRUH + l) * HID + k], 0.f);
    }
}

// ---------------- feature -> bf16 ----------------
__global__ void f2b(const float* __restrict__ src, __nv_bfloat16* __restrict__ dst, int n4) {
    int i = blockIdx.x * blockDim.x + threadIdx.x;
    if (i < n4) {
        float4 v = ((const float4*)src)[i];
        uint2 o;
        o.x = bf16u(v.x) | (bf16u(v.y) << 16);
        o.y = bf16u(v.z) | (bf16u(v.w) << 16);
        ((uint2*)dst)[i] = o;
    }
}

// -------- single-block deterministic bucketing (desc degree, batches of 16) --------
__global__ void k_bucket(const int* __restrict__ deg) {
    __shared__ unsigned short cnts[512][16];
    __shared__ int btot[16], binbase[16];
    int tid = threadIdx.x;
    int lc[16];
#pragma unroll
    for (int b = 0; b < 16; ++b) lc[b] = 0;
    for (int i = tid; i < NNODES; i += 512) lc[deg[i] - 1]++;
#pragma unroll
    for (int b = 0; b < 16; ++b) cnts[tid][b] = (unsigned short)lc[b];
    __syncthreads();
    if (tid < 16) {
        int run = 0;
        for (int j = 0; j < 512; ++j) {
            int v = cnts[j][tid];
            cnts[j][tid] = (unsigned short)run;
            run += v;
        }
        btot[tid] = run;
    }
    __syncthreads();
    if (tid == 0) {
        int off = 0;
        for (int b = 0; b < 16; ++b) { binbase[b] = off; off += btot[b]; }
        int bo = 0;
        for (int b = 15; b >= 0; --b) {
            for (int j = 0; j < btot[b]; j += 16, ++bo) {
                g_batch_start[bo] = binbase[b] + j;
                g_batch_info[bo]  = ((b + 1) << 8) | min(16, btot[b] - j);
            }
        }
        g_nbatch = bo;
    }
    __syncthreads();
#pragma unroll
    for (int b = 0; b < 16; ++b) lc[b] = binbase[b] + cnts[tid][b];
    for (int i = tid; i < NNODES; i += 512) {
        int d = deg[i] - 1;
        g_order[lc[d]++] = i;
    }
}

// ---------------- bf16 HMMA GEMM, K=128 (x2 passes), fused bias/act ----------------
// C[M,N] = act(A1@W1 [+ A2@W2] + bias). W prepacked fragments. 256 thr, 32-row tiles.
#define AS 136   // astage row stride in shorts

__global__ __launch_bounds__(256, 2)
void hgemm(const __nv_bfloat16* __restrict__ A1, const __nv_bfloat16* __restrict__ A2,
           const uint2* __restrict__ W1, const uint2* __restrict__ W2,
           const float* __restrict__ bias, void* __restrict__ out,
           int M, int N, int relu, int obf16) {
    extern __shared__ char sm[];
    int NG = N >> 3;
    int nw = 8 * NG * 32;                      // uint2 per matrix
    int npass = (A2 != nullptr) ? 2 : 1;
    uint2* wf1 = (uint2*)sm;
    uint2* wf2 = wf1 + nw;
    unsigned short* ast = (unsigned short*)(wf1 + (size_t)npass * nw);
    float* bsm = (float*)(ast + npass * 32 * AS);

    int tid = threadIdx.x, wid = tid >> 5, lane = tid & 31;
    {
        uint4* d = (uint4*)wf1;
        const uint4* s = (const uint4*)W1;
        for (int i = tid; i < nw / 2; i += 256) d[i] = s[i];
        if (npass == 2) {
            uint4* d2 = (uint4*)wf2;
            const uint4* s2 = (const uint4*)W2;
            for (int i = tid; i < nw / 2; i += 256) d2[i] = s2[i];
        }
    }
    if (bias) for (int i = tid; i < N; i += 256) bsm[i] = bias[i];

    int rh = wid & 1, cc = wid >> 1;
    int gpw = NG >> 2;
    int r0 = lane >> 2, q = lane & 3;
    int nbat = (M + 31) >> 5;
    int lrow = tid >> 3, lch = tid & 7;

    uint4 pf[2][2];
    int bi = blockIdx.x;
    if (bi < nbat) {
        int gr = min(bi * 32 + lrow, M - 1);
        const uint4* s = (const uint4*)(A1 + (size_t)gr * 128 + lch * 16);
        pf[0][0] = s[0]; pf[0][1] = s[1];
        if (npass == 2) {
            const uint4* s2 = (const uint4*)(A2 + (size_t)gr * 128 + lch * 16);
            pf[1][0] = s2[0]; pf[1][1] = s2[1];
        }
    }
    __syncthreads();

    for (; bi < nbat; bi += gridDim.x) {
        // stage current tile
        {
            uint4* d = (uint4*)(ast + lrow * AS + lch * 16);
            d[0] = pf[0][0]; d[1] = pf[0][1];
            if (npass == 2) {
                uint4* d2 = (uint4*)(ast + 32 * AS + lrow * AS + lch * 16);
                d2[0] = pf[1][0]; d2[1] = pf[1][1];
            }
        }
        __syncthreads();
        // prefetch next tile
        int bn = bi + gridDim.x;
        if (bn < nbat) {
            int gr = min(bn * 32 + lrow, M - 1);
            const uint4* s = (const uint4*)(A1 + (size_t)gr * 128 + lch * 16);
            pf[0][0] = s[0]; pf[0][1] = s[1];
            if (npass == 2) {
                const uint4* s2 = (const uint4*)(A2 + (size_t)gr * 128 + lch * 16);
                pf[1][0] = s2[0]; pf[1][1] = s2[1];
            }
        }
        // a-fragments
        unsigned a1[8][4], a2[8][4];
        {
            const unsigned short* base = ast + (rh * 16) * AS;
#pragma unroll
            for (int kt = 0; kt < 8; ++kt) {
                const unsigned short* hb = base + kt * 16 + q * 2;
                a1[kt][0] = *(const unsigned*)(hb + r0 * AS);
                a1[kt][1] = *(const unsigned*)(hb + (r0 + 8) * AS);
                a1[kt][2] = *(const unsigned*)(hb + r0 * AS + 8);
                a1[kt][3] = *(const unsigned*)(hb + (r0 + 8) * AS + 8);
            }
            if (npass == 2) {
                const unsigned short* b2 = base + 32 * AS;
#pragma unroll
                for (int kt = 0; kt < 8; ++kt) {
                    const unsigned short* hb = b2 + kt * 16 + q * 2;
                    a2[kt][0] = *(const unsigned*)(hb + r0 * AS);
                    a2[kt][1] = *(const unsigned*)(hb + (r0 + 8) * AS);
                    a2[kt][2] = *(const unsigned*)(hb + r0 * AS + 8);
                    a2[kt][3] = *(const unsigned*)(hb + (r0 + 8) * AS + 8);
                }
            }
        }
        int gr0b = bi * 32 + rh * 16 + r0;
        for (int g = 0; g < gpw; ++g) {
            int gg = cc * gpw + g;
            float acc[4] = {0.f, 0.f, 0.f, 0.f};
#pragma unroll
            for (int kt = 0; kt < 8; ++kt) {
                uint2 b = wf1[(kt * NG + gg) * 32 + lane];
                mma16816(acc, a1[kt], b.x, b.y);
            }
            if (npass == 2) {
#pragma unroll
                for (int kt = 0; kt < 8; ++kt) {
                    uint2 b = wf2[(kt * NG + gg) * 32 + lane];
                    mma16816(acc, a2[kt], b.x, b.y);
                }
            }
            int c0 = gg * 8 + 2 * q;
            float b0 = 0.f, b1 = 0.f;
            if (bias) { b0 = bsm[c0]; b1 = bsm[c0 + 1]; }
            float o0 = acc[0] + b0, o1 = acc[1] + b1, o2 = acc[2] + b0, o3 = acc[3] + b1;
            if (relu) {
                o0 = fmaxf(o0, 0.f); o1 = fmaxf(o1, 0.f);
                o2 = fmaxf(o2, 0.f); o3 = fmaxf(o3, 0.f);
            }
            int gr1 = gr0b + 8;
            if (obf16) {
                unsigned w0 = bf16u(o0) | (bf16u(o1) << 16);
                unsigned w1 = bf16u(o2) | (bf16u(o3) << 16);
                if (gr0b < M) *(unsigned*)((__nv_bfloat16*)out + (size_t)gr0b * N + c0) = w0;
                if (gr1  < M) *(unsigned*)((__nv_bfloat16*)out + (size_t)gr1  * N + c0) = w1;
            } else {
                if (gr0b < M) *(float2*)((float*)out + (size_t)gr0b * N + c0) = make_float2(o0, o1);
                if (gr1  < M) *(float2*)((float*)out + (size_t)gr1  * N + c0) = make_float2(o2, o3);
            }
        }
        __syncthreads();
    }
}

// ------- mma.sync LSTM: 4-warp groups, 4 groups/CTA, double-buffered h -------
#define LGROUPS 4
#define HSTRIDE 136
#define SM_WF    0                                   // 131072
#define SM_BIAS  131072                              // 2048
#define SM_HSTG  133120                              // 34816
#define SM_NID   (SM_HSTG + 34816)                   // 256
#define SM_USM   (SM_NID + 256)                      // 4096
#define SM_TOTAL (SM_USM + 4096)

__global__ __launch_bounds__(512, 1)
void lstm_mma(const int* __restrict__ nbr) {
    extern __shared__ char smr[];
    uint4*  wf  = (uint4*)(smr + SM_WF);
    float4* bsm = (float4*)(smr + SM_BIAS);
    __nv_bfloat16* hstg = (__nv_bfloat16*)(smr + SM_HSTG);
    int* nidA = (int*)(smr + SM_NID);
    int* usmA = (int*)(smr + SM_USM);

    int tid = threadIdx.x, wid = tid >> 5, lane = tid & 31;
    for (int i = tid; i < 256 * 32; i += 512) wf[i] = g_Wfrag4[i];
    if (tid < HID) bsm[tid] = g_biasF[tid];
    __syncthreads();

    int grp = wid >> 2, chunk = wid & 3;
    __nv_bfloat16* hs0 = hstg + grp * 2 * 16 * HSTRIDE;
    __nv_bfloat16* hs1 = hs0 + 16 * HSTRIDE;
    int* mynid = nidA + grp * 16;
    int* usm   = usmA + grp * 16 * MAXD;
    int r0 = lane >> 2, q = lane & 3;
    int barid = grp + 1;
    int nb = g_nbatch;
    const unsigned* PB = (const unsigned*)g_Pb;

    for (int b = blockIdx.x * LGROUPS + grp; b < nb; b += gridDim.x * LGROUPS) {
        asm volatile("bar.sync %0, %1;" :: "r"(barid), "r"(128) : "memory");
        int start = g_batch_start[b];
        int info  = g_batch_info[b];
        int dmax = info >> 8, cnt = info & 255;
        if (chunk == 0 && lane < 16) {
            int nid = g_order[start + min(lane, cnt - 1)];
            mynid[lane] = nid;
            const int4* src = (const int4*)(nbr + nid * MAXD);
            int4* dst = (int4*)(usm + lane * MAXD);
            dst[0] = src[0]; dst[1] = src[1]; dst[2] = src[2]; dst[3] = src[3];
        }
        asm volatile("bar.sync %0, %1;" :: "r"(barid), "r"(128) : "memory");

        float cst[16];
#pragma unroll
        for (int i = 0; i < 16; ++i) cst[i] = 0.f;

        unsigned pnl[16];
        {
            const unsigned* L = PB + (size_t)usm[r0 * MAXD] * 256;
#pragma unroll
            for (int nt = 0; nt < 16; ++nt) pnl[nt] = L[chunk * 64 + nt * 4 + q];
        }

        for (int t = 0; t < dmax; ++t) {
            asm volatile("bar.sync %0, %1;" :: "r"(barid), "r"(128) : "memory");
            const __nv_bfloat16* hsR = (t & 1) ? hs0 : hs1;
            __nv_bfloat16*       hsW = (t & 1) ? hs1 : hs0;

            unsigned a[8][4];
            if (t > 0) {
#pragma unroll
                for (int kt = 0; kt < 8; ++kt) {
                    const __nv_bfloat16* hb = hsR + kt * 16 + q * 2;
                    a[kt][0] = *(const unsigned*)(hb + r0 * HSTRIDE);
                    a[kt][1] = *(const unsigned*)(hb + (r0 + 8) * HSTRIDE);
                    a[kt][2] = *(const unsigned*)(hb + r0 * HSTRIDE + 8);
                    a[kt][3] = *(const unsigned*)(hb + (r0 + 8) * HSTRIDE + 8);
                }
            }
            unsigned pcl[16];
#pragma unroll
            for (int nt = 0; nt < 16; ++nt) pcl[nt] = pnl[nt];
            unsigned pch[16];
            {
                const unsigned* H = PB + (size_t)usm[(r0 + 8) * MAXD + t] * 256;
#pragma unroll
                for (int nt = 0; nt < 16; ++nt) pch[nt] = H[chunk * 64 + nt * 4 + q];
            }
            if (t + 1 < dmax) {
                const unsigned* L = PB + (size_t)usm[r0 * MAXD + t + 1] * 256;
#pragma unroll
                for (int nt = 0; nt < 16; ++nt) pnl[nt] = L[chunk * 64 + nt * 4 + q];
            }

            bool last = (t == dmax - 1);
#pragma unroll
            for (int p = 0; p < 8; ++p) {
                float aE[4] = {0.f, 0.f, 0.f, 0.f};
                float aO[4] = {0.f, 0.f, 0.f, 0.f};
                if (t > 0) {
#pragma unroll
                    for (int kt = 0; kt < 8; ++kt) {
                        uint4 bb = wf[((kt << 5) | (chunk << 3) | p) * 32 + lane];
                        mma16816(aE, a[kt], bb.x, bb.y);
                        mma16816(aO, a[kt], bb.z, bb.w);
                    }
                }
                int J = chunk * 32 + p * 4 + q;
                float4 bs = bsm[J];
                {
                    float gi = aE[0] + blo(pcl[2 * p])     + bs.x;
                    float gf = aE[1] + bhi(pcl[2 * p])     + bs.y;
                    float gg = aO[0] + blo(pcl[2 * p + 1]) + bs.z;
                    float go = aO[1] + bhi(pcl[2 * p + 1]) + bs.w;
                    float cn = sigt(gf) * cst[2 * p] + sigt(gi) * tanhap(gg);
                    cst[2 * p] = cn;
                    float h = sigt(go) * tanhap(cn);
                    if (!last) hsW[r0 * HSTRIDE + J] = __float2bfloat16(h);
                    else if (r0 < cnt) g_hTb[(size_t)mynid[r0] * HID + J] = __float2bfloat16(h);
                }
                {
                    float gi = aE[2] + blo(pch[2 * p])     + bs.x;
                    float gf = aE[3] + bhi(pch[2 * p])     + bs.y;
                    float gg = aO[2] + blo(pch[2 * p + 1]) + bs.z;
                    float go = aO[3] + bhi(pch[2 * p + 1]) + bs.w;
                    float cn = sigt(gf) * cst[2 * p + 1] + sigt(gi) * tanhap(gg);
                    cst[2 * p + 1] = cn;
                    float h = sigt(go) * tanhap(cn);
                    if (!last) hsW[(r0 + 8) * HSTRIDE + J] = __float2bfloat16(h);
                    else if (r0 + 8 < cnt) g_hTb[(size_t)mynid[r0 + 8] * HID + J] = __float2bfloat16(h);
                }
            }
        }
    }
}

// ---------------- GraphConv aggregate (bf16 in/out) ----------------
__global__ void agg_kernel(const int* __restrict__ nbr, const int* __restrict__ deg) {
    int wid  = (blockIdx.x * blockDim.x + threadIdx.x) >> 5;
    int lane = threadIdx.x & 31;
    if (wid >= NNODES) return;
    int d = deg[wid];
    const int* nb = nbr + wid * MAXD;
    float a0 = 0.f, a1 = 0.f, a2 = 0.f, a3 = 0.f;
    for (int t = 0; t < d; ++t) {
        int u = nb[t];
        float nu = rsqrtf((float)max(deg[u], 1));
        uint2 v = *(const uint2*)(g_h1b + (size_t)u * 128 + lane * 4);
        a0 = fmaf(blo(v.x), nu, a0); a1 = fmaf(bhi(v.x), nu, a1);
        a2 = fmaf(blo(v.y), nu, a2); a3 = fmaf(bhi(v.y), nu, a3);
    }
    float nn = rsqrtf((float)max(d, 1));
    uint2 o;
    o.x = bf16u(a0 * nn) | (bf16u(a1 * nn) << 16);
    o.y = bf16u(a2 * nn) | (bf16u(a3 * nn) << 16);
    *(uint2*)(g_aggB + (size_t)wid * 128 + lane * 4) = o;
}

// ---------------- GRU ----------------
__global__ void gru_kernel(const float* __restrict__ bih, const float* __restrict__ bhh) {
    extern __shared__ char sm[];
    float4* Wt   = (float4*)sm;
    float*  hrow = (float*)(sm + 65536);
    int tid = threadIdx.x;
    for (int i = tid; i < HID * GRUH; i += blockDim.x) Wt[i] = g_Wt3[i];
    __syncthreads();

    int w = tid >> 5, lane = tid & 31;
    float br = bih[lane], bz = bih[32 + lane], bn = bih[64 + lane];
    float cr = bhh[lane], cz = bhh[32 + lane], cnb = bhh[64 + lane];
    float* hr = hrow + w * 128;
    int nwarp = gridDim.x * 8;
    for (int node = blockIdx.x * 8 + w; node < NNODES; node += nwarp) {
        const float* h2 = g_h2 + (size_t)node * 128;
        *(float4*)(hr + lane * 4) = *(const float4*)(h2 + lane * 4);
        __syncwarp();
        float ar = 0.f, az = 0.f, an = 0.f;
#pragma unroll 8
        for (int k = 0; k < 128; ++k) {
            float hk = hr[k];
            float4 wv = Wt[k * 32 + lane];
            ar = fmaf(hk, wv.x, ar);
            az = fmaf(hk, wv.y, az);
            an = fmaf(hk, wv.z, an);
        }
        __syncwarp();
        float r   = sigf(ar + br + cr);
        float z   = sigf(az + bz + cz);
        float nst = tanh_(an + bn + r * cnb);
        g_o32[(size_t)node * 32 + lane] = (1.f - z) * nst;
    }
}

// ---------------- mean pool + classifier ----------------
__global__ void pool_kernel(const int* __restrict__ gid,
                            const float* __restrict__ Wc,
                            const float* __restrict__ bc,
                            float* __restrict__ out) {
    __shared__ float s[8][32];
    __shared__ int   scnt[8];
    __shared__ float hg[32];
    int g = blockIdx.x;
    int tid = threadIdx.x, lane = tid & 31, slot = tid >> 5;
    float acc = 0.f;
    int cnt = 0;
    for (int i = slot; i < NNODES; i += 8) {
        if (gid[i] == g) {
            acc += g_o32[(size_t)i * 32 + lane];
            cnt++;
        }
    }
    s[slot][lane] = acc;
    if (lane == 0) scnt[slot] = cnt;
    __syncthreads();
    if (tid < 32) {
        float sum = 0.f; int tot = 0;
#pragma unroll
        for (int j = 0; j < 8; ++j) { sum += s[j][tid]; tot += scnt[j]; }
        hg[tid] = sum / (float)tot;
    }
    __syncthreads();
    if (tid < NCLS) {
        float o = bc[tid];
#pragma unroll
        for (int k = 0; k < 32; ++k) o = fmaf(hg[k], Wc[k * NCLS + tid], o);
        out[g * NCLS + tid] = o;
    }
}

// ---------------- launch ----------------
extern "C" void kernel_launch(void* const* d_in, const int* in_sizes, int n_in,
                              void* d_out, int out_size) {
    const float* feature = (const float*)d_in[0];
    const int*   nbr     = (const int*)  d_in[1];
    const int*   deg     = (const int*)  d_in[2];
    const int*   gid     = (const int*)  d_in[3];
    const float* lWih    = (const float*)d_in[4];
    const float* lWhh    = (const float*)d_in[5];
    const float* lbih    = (const float*)d_in[6];
    const float* lbhh    = (const float*)d_in[7];
    const float* Wself   = (const float*)d_in[8];
    const float* Wneigh  = (const float*)d_in[9];
    const float* bsage   = (const float*)d_in[10];
    const float* Wgc     = (const float*)d_in[11];
    const float* bgc     = (const float*)d_in[12];
    const float* Wgru    = (const float*)d_in[13];
    const float* bihg    = (const float*)d_in[14];
    const float* bhhg    = (const float*)d_in[15];
    const float* Wcls    = (const float*)d_in[16];
    const float* bcls    = (const float*)d_in[17];
    float* out = (float*)d_out;

    // smem sizes for hgemm variants
    const int smP = 16384 * 8 + 32 * AS * 2 + 256;            // 1 pass, N=512
    const int smS = 2 * 4096 * 8 + 2 * 32 * AS * 2 + 512 + 256; // 2 pass, N=128
    const int smG = 4096 * 8 + 32 * AS * 2 + 512 + 256;       // 1 pass, N=128

    cudaFuncSetAttribute(hgemm, cudaFuncAttributeMaxDynamicSharedMemorySize, smP);
    cudaFuncSetAttribute(lstm_mma, cudaFuncAttributeMaxDynamicSharedMemorySize, SM_TOTAL);
    cudaFuncSetAttribute(gru_kernel, cudaFuncAttributeMaxDynamicSharedMemorySize, 69632 + 256);

    void *pPb, *pFeatB, *pHtb, *pH1b, *pAggB, *pH2;
    void *pWfP, *pWfSelf, *pWfNeigh, *pWfGc;
    cudaGetSymbolAddress(&pPb,     g_Pb);
    cudaGetSymbolAddress(&pFeatB,  g_featB);
    cudaGetSymbolAddress(&pHtb,    g_hTb);
    cudaGetSymbolAddress(&pH1b,    g_h1b);
    cudaGetSymbolAddress(&pAggB,   g_aggB);
    cudaGetSymbolAddress(&pH2,     g_h2);
    cudaGetSymbolAddress(&pWfP,    g_WfP);
    cudaGetSymbolAddress(&pWfSelf, g_WfSelf);
    cudaGetSymbolAddress(&pWfNeigh,g_WfNeigh);
    cudaGetSymbolAddress(&pWfGc,   g_WfGc);

    // 1. pack all weights
    prep_kernel<<<256, 256>>>(lWih, lWhh, lbih, lbhh, Wself, Wneigh, Wgc, Wgru);
    // 2. feature -> bf16
    f2b<<<(NNODES * 128 / 4 + 255) / 256, 256>>>(feature, (__nv_bfloat16*)pFeatB, NNODES * 128 / 4);
    // 3. P = featB @ WihT(perm)  -> bf16 [N,512]
    hgemm<<<152, 256, smP>>>((const __nv_bfloat16*)pFeatB, nullptr,
                             (const uint2*)pWfP, nullptr, nullptr, pPb,
                             NNODES, 512, 0, 1);
    // 4. deterministic bucketing
    k_bucket<<<1, 512>>>(deg);
    // 5. LSTM recurrence
    lstm_mma<<<152, 512, SM_TOTAL>>>(nbr);
    // 6. h1 = relu(featB@Wself + hTb@Wneigh + b_sage) -> bf16
    hgemm<<<304, 256, smS>>>((const __nv_bfloat16*)pFeatB, (const __nv_bfloat16*)pHtb,
                             (const uint2*)pWfSelf, (const uint2*)pWfNeigh, bsage, pH1b,
                             NNODES, 128, 1, 1);
    // 7. GraphConv aggregate
    agg_kernel<<<(NNODES * 32 + 255) / 256, 256>>>(nbr, deg);
    // 8. h2 = relu(aggB @ Wgc + b_gc) -> fp32
    hgemm<<<304, 256, smG>>>((const __nv_bfloat16*)pAggB, nullptr,
                             (const uint2*)pWfGc, nullptr, bgc, pH2,
                             NNODES, 128, 1, 0);
    // 9. GRU
    gru_kernel<<<304, 256, 69632 + 256>>>(bihg, bhhg);
    // 10. mean pool + classifier
    pool_kernel<<<NGRAPH, 256>>>(gid, Wcls, bcls, out);
}

// round 12
// speedup vs baseline: 1.7698x; 1.4401x over previous
#include <cuda_runtime.h>
#include <cuda_bf16.h>
#include <cstdint>

#define NNODES 50000
#define HID    128
#define MAXD   16
#define NGRAPH 50
#define NCLS   10
#define GRUH   32
#define MAXB   3400

// ---------------- scratch ----------------
__device__ __nv_bfloat16 g_Pb [(size_t)NNODES * 512];
__device__ __nv_bfloat16 g_featB[(size_t)NNODES * HID];
__device__ __nv_bfloat16 g_hTb [(size_t)NNODES * HID];
__device__ __nv_bfloat16 g_h1b [(size_t)NNODES * HID];
__device__ __nv_bfloat16 g_aggB[(size_t)NNODES * HID];
__device__ float g_h2 [(size_t)NNODES * HID];
__device__ float g_o32[(size_t)NNODES * GRUH];
__device__ uint2 g_WfP[16384];               // Wih fragments (N=512, permuted cols, kt-major)
__device__ uint2 g_WfSelf[4096];
__device__ uint2 g_WfNeigh[4096];
__device__ uint2 g_WfGc[4096];
__device__ uint4 g_Wfrag4[256 * 32];         // lstm Whh fragments, E/O fused
__device__ float4 g_biasF[HID];              // (bi,bf,bg,bo)
__device__ float4 g_Wt3 [HID * GRUH];        // GRU weights fp32
__device__ float g_pp[NGRAPH][4][32];
__device__ int   g_pc[NGRAPH][4];
// degree bucketing
__device__ int g_order[NNODES];
__device__ int g_batch_start[MAXB];
__device__ int g_batch_info[MAXB];
__device__ int g_nbatch;

// ---------------- helpers ----------------
__device__ __forceinline__ float sigf(float x) {
    x = fminf(fmaxf(x, -30.f), 30.f);
    return __fdividef(1.f, 1.f + __expf(-x));
}
__device__ __forceinline__ float tanh_(float x) {
    x = fminf(fmaxf(x, -15.f), 15.f);
    float e = __expf(-2.f * x);
    return __fdividef(1.f - e, 1.f + e);
}
__device__ __forceinline__ float tanhap(float x) {
    float y; asm("tanh.approx.f32 %0, %1;" : "=f"(y) : "f"(x)); return y;
}
__device__ __forceinline__ float sigt(float x) { return fmaf(tanhap(x * 0.5f), 0.5f, 0.5f); }
__device__ __forceinline__ unsigned bf16u(float x) {
    __nv_bfloat16 b = __float2bfloat16(x);
    return (unsigned)*reinterpret_cast<unsigned short*>(&b);
}
__device__ __forceinline__ float blo(unsigned v) { return __uint_as_float(v << 16); }
__device__ __forceinline__ float bhi(unsigned v) { return __uint_as_float(v & 0xFFFF0000u); }

__host__ __device__ __forceinline__ int phys2row(int p) {
    int pb = p >> 4, rem = p & 15;
    int gamma, aa;
    if (rem < 8) { aa = rem >> 1; gamma = (rem & 1) ? 1 : 0; }
    else         { aa = (rem - 8) >> 1; gamma = (rem & 1) ? 3 : 2; }
    return gamma * HID + pb * 4 + aa;
}

__device__ __forceinline__ void mma16816(float* d, const unsigned* a, unsigned b0, unsigned b1) {
    asm volatile(
        "mma.sync.aligned.m16n8k16.row.col.f32.bf16.bf16.f32 "
        "{%0,%1,%2,%3}, {%4,%5,%6,%7}, {%8,%9}, {%0,%1,%2,%3};"
        : "+f"(d[0]), "+f"(d[1]), "+f"(d[2]), "+f"(d[3])
        : "r"(a[0]), "r"(a[1]), "r"(a[2]), "r"(a[3]), "r"(b0), "r"(b1));
}

// ---------------- prep: all weight packing ----------------
__global__ void prep_kernel(const float* __restrict__ Wih,
                            const float* __restrict__ Whh,
                            const float* __restrict__ bih,
                            const float* __restrict__ bhh,
                            const float* __restrict__ Wself,
                            const float* __restrict__ Wneigh,
                            const float* __restrict__ Wgc,
                            const float* __restrict__ Wgru) {
    int idx = blockIdx.x * blockDim.x + threadIdx.x;
    if (idx < 16384) {
        int l = idx & 31, t = idx >> 5;
        int kt = t >> 6, g = t & 63;
        int n = g * 8 + (l >> 2);
        int k0 = kt * 16 + (l & 3) * 2;
        int r = phys2row(n) * HID;
        uint2 v;
        v.x = bf16u(Wih[r + k0])     | (bf16u(Wih[r + k0 + 1]) << 16);
        v.y = bf16u(Wih[r + k0 + 8]) | (bf16u(Wih[r + k0 + 9]) << 16);
        g_WfP[idx] = v;
    }
    if (idx < 4096) {
        int l = idx & 31, t = idx >> 5;
        int kt = t >> 4, g = t & 15;
        int n = g * 8 + (l >> 2);
        int k0 = kt * 16 + (l & 3) * 2;
        uint2 v;
        v.x = bf16u(Wself[k0 * HID + n])       | (bf16u(Wself[(k0 + 1) * HID + n]) << 16);
        v.y = bf16u(Wself[(k0 + 8) * HID + n]) | (bf16u(Wself[(k0 + 9) * HID + n]) << 16);
        g_WfSelf[idx] = v;
        v.x = bf16u(Wneigh[k0 * HID + n])       | (bf16u(Wneigh[(k0 + 1) * HID + n]) << 16);
        v.y = bf16u(Wneigh[(k0 + 8) * HID + n]) | (bf16u(Wneigh[(k0 + 9) * HID + n]) << 16);
        g_WfNeigh[idx] = v;
        v.x = bf16u(Wgc[k0 * HID + n])       | (bf16u(Wgc[(k0 + 1) * HID + n]) << 16);
        v.y = bf16u(Wgc[(k0 + 8) * HID + n]) | (bf16u(Wgc[(k0 + 9) * HID + n]) << 16);
        g_WfGc[idx] = v;
    }
    if (idx < 512 * 32) {
        int t_id = idx >> 5, lane = idx & 31;
        int kt = t_id >> 6, ntg = t_id & 63;
        int p = ntg * 8 + (lane >> 2);
        int wrow = phys2row(p);
        int k0 = kt * 16 + (lane & 3) * 2;
        const float* wr = Whh + (size_t)wrow * HID;
        uint2 v;
        v.x = bf16u(wr[k0])     | (bf16u(wr[k0 + 1]) << 16);
        v.y = bf16u(wr[k0 + 8]) | (bf16u(wr[k0 + 9]) << 16);
        int chunk = ntg >> 4, nt = ntg & 15;
        int pp = nt >> 1, isO = nt & 1;
        int dst = (((kt << 5) | (chunk << 3) | pp) * 32 + lane) * 2 + isO;
        ((uint2*)g_Wfrag4)[dst] = v;
    }
    if (idx < HID) {
        g_biasF[idx] = make_float4(bih[idx] + bhh[idx],
                                   bih[HID + idx] + bhh[HID + idx],
                                   bih[2 * HID + idx] + bhh[2 * HID + idx],
                                   bih[3 * HID + idx] + bhh[3 * HID + idx]);
    }
    if (idx < HID * GRUH) {
        int k = idx >> 5, l = idx & 31;
        g_Wt3[idx] = make_float4(Wgru[(0 * GRUH + l) * HID + k],
                                 Wgru[(1 * GRUH + l) * HID + k],
                                 Wgru[(2 * GRUH + l) * HID + k], 0.f);
    }
}

// ---------------- feature -> bf16 ----------------
__global__ void f2b(const float* __restrict__ src, __nv_bfloat16* __restrict__ dst, int n4) {
    int i = blockIdx.x * blockDim.x + threadIdx.x;
    if (i < n4) {
        float4 v = ((const float4*)src)[i];
        uint2 o;
        o.x = bf16u(v.x) | (bf16u(v.y) << 16);
        o.y = bf16u(v.z) | (bf16u(v.w) << 16);
        ((uint2*)dst)[i] = o;
    }
}

// -------- single-block deterministic bucketing, parallelized --------
__global__ void k_bucket(const int* __restrict__ deg) {
    __shared__ unsigned short cnts[512][16];
    __shared__ int btot[16], binbase[16], bOffD[16];
    __shared__ int nbatch_s;
    int tid = threadIdx.x, lane = tid & 31, w = tid >> 5;
    int lc[16];
#pragma unroll
    for (int b = 0; b < 16; ++b) lc[b] = 0;
    for (int i = tid; i < NNODES; i += 512) lc[deg[i] - 1]++;
#pragma unroll
    for (int b = 0; b < 16; ++b) cnts[tid][b] = (unsigned short)lc[b];
    __syncthreads();
    {
        int run = 0;
        for (int c = 0; c < 16; ++c) {
            int j = c * 32 + lane;
            int v = cnts[j][w];
            int s = v;
#pragma unroll
            for (int off = 1; off < 32; off <<= 1) {
                int t2 = __shfl_up_sync(0xFFFFFFFFu, s, off);
                if (lane >= off) s += t2;
            }
            cnts[j][w] = (unsigned short)(run + s - v);
            run += __shfl_sync(0xFFFFFFFFu, s, 31);
        }
        if (lane == 0) btot[w] = run;
    }
    __syncthreads();
    if (tid == 0) {
        int off = 0;
        for (int b = 0; b < 16; ++b) { binbase[b] = off; off += btot[b]; }
        int bo = 0;
        for (int b = 15; b >= 0; --b) { bOffD[b] = bo; bo += (btot[b] + 15) >> 4; }
        nbatch_s = bo;
        g_nbatch = bo;
    }
    __syncthreads();
    int nb = nbatch_s;
    for (int bi = tid; bi < nb; bi += 512) {
        int bin = 0;
#pragma unroll
        for (int b = 15; b >= 0; --b) {
            int nbb = (btot[b] + 15) >> 4;
            if (bi >= bOffD[b] && bi < bOffD[b] + nbb) { bin = b; break; }
        }
        int j = (bi - bOffD[bin]) * 16;
        g_batch_start[bi] = binbase[bin] + j;
        g_batch_info[bi]  = ((bin + 1) << 8) | min(16, btot[bin] - j);
    }
#pragma unroll
    for (int b = 0; b < 16; ++b) lc[b] = binbase[b] + cnts[tid][b];
    for (int i = tid; i < NNODES; i += 512) {
        int d = deg[i] - 1;
        g_order[lc[d]++] = i;
    }
}

// ---------------- bf16 HMMA GEMM, K=128, dual accumulation chains ----------------
#define AS 136

__global__ __launch_bounds__(256, 2)
void hgemm(const __nv_bfloat16* __restrict__ A1, const __nv_bfloat16* __restrict__ A2,
           const uint2* __restrict__ W1, const uint2* __restrict__ W2,
           const float* __restrict__ bias, void* __restrict__ out,
           int M, int N, int relu, int obf16, int splits) {
    extern __shared__ char sm[];
    int Nc = N / splits;
    int NG = Nc >> 3;
    int NGfull = N >> 3;
    int nw = 8 * NG * 32;
    int sp = blockIdx.x & (splits - 1);
    int cbase = sp * Nc;
    int nCTA = gridDim.x >> (splits - 1);
    int npass = (A2 != nullptr) ? 2 : 1;
    uint2* wf1 = (uint2*)sm;
    uint2* wf2 = wf1 + nw;
    unsigned short* ast = (unsigned short*)(wf1 + (size_t)npass * nw);
    float* bsm = (float*)(ast + npass * 32 * AS);

    int tid = threadIdx.x, wid = tid >> 5, lane = tid & 31;
    {
        // gather this split's fragments: local (kt*NG+gg) <- global (kt*NGfull + sp*NG + gg)
        for (int i = tid; i < nw; i += 256) {
            int t2 = i >> 5, li = i & 31;
            int kt = t2 / NG, gg = t2 - kt * NG;
            int src = (kt * NGfull + sp * NG + gg) * 32 + li;
            wf1[i] = W1[src];
            if (npass == 2) wf2[i] = W2[src];
        }
    }
    if (bias) for (int i = tid; i < Nc; i += 256) bsm[i] = bias[cbase + i];

    int rh = wid & 1, cc = wid >> 1;
    int gpw = NG >> 2;
    int r0 = lane >> 2, q = lane & 3;
    int nbat = (M + 31) >> 5;
    int lrow = tid >> 3, lch = tid & 7;

    uint4 pf[2][2];
    int bi = blockIdx.x >> (splits - 1);
    if (bi < nbat) {
        int gr = min(bi * 32 + lrow, M - 1);
        const uint4* s = (const uint4*)(A1 + (size_t)gr * 128 + lch * 16);
        pf[0][0] = s[0]; pf[0][1] = s[1];
        if (npass == 2) {
            const uint4* s2 = (const uint4*)(A2 + (size_t)gr * 128 + lch * 16);
            pf[1][0] = s2[0]; pf[1][1] = s2[1];
        }
    }
    __syncthreads();

    for (; bi < nbat; bi += nCTA) {
        {
            uint4* d = (uint4*)(ast + lrow * AS + lch * 16);
            d[0] = pf[0][0]; d[1] = pf[0][1];
            if (npass == 2) {
                uint4* d2 = (uint4*)(ast + 32 * AS + lrow * AS + lch * 16);
                d2[0] = pf[1][0]; d2[1] = pf[1][1];
            }
        }
        __syncthreads();
        int bn = bi + nCTA;
        if (bn < nbat) {
            int gr = min(bn * 32 + lrow, M - 1);
            const uint4* s = (const uint4*)(A1 + (size_t)gr * 128 + lch * 16);
            pf[0][0] = s[0]; pf[0][1] = s[1];
            if (npass == 2) {
                const uint4* s2 = (const uint4*)(A2 + (size_t)gr * 128 + lch * 16);
                pf[1][0] = s2[0]; pf[1][1] = s2[1];
            }
        }
        unsigned a1[8][4], a2[8][4];
        {
            const unsigned short* base = ast + (rh * 16) * AS;
#pragma unroll
            for (int kt = 0; kt < 8; ++kt) {
                const unsigned short* hb = base + kt * 16 + q * 2;
                a1[kt][0] = *(const unsigned*)(hb + r0 * AS);
                a1[kt][1] = *(const unsigned*)(hb + (r0 + 8) * AS);
                a1[kt][2] = *(const unsigned*)(hb + r0 * AS + 8);
                a1[kt][3] = *(const unsigned*)(hb + (r0 + 8) * AS + 8);
            }
            if (npass == 2) {
                const unsigned short* b2 = base + 32 * AS;
#pragma unroll
                for (int kt = 0; kt < 8; ++kt) {
                    const unsigned short* hb = b2 + kt * 16 + q * 2;
                    a2[kt][0] = *(const unsigned*)(hb + r0 * AS);
                    a2[kt][1] = *(const unsigned*)(hb + (r0 + 8) * AS);
                    a2[kt][2] = *(const unsigned*)(hb + r0 * AS + 8);
                    a2[kt][3] = *(const unsigned*)(hb + (r0 + 8) * AS + 8);
                }
            }
        }
        int gr0b = bi * 32 + rh * 16 + r0;
        for (int g = 0; g < gpw; ++g) {
            int gg = cc * gpw + g;
            float acc[4] = {0.f, 0.f, 0.f, 0.f};
            float acb[4] = {0.f, 0.f, 0.f, 0.f};
#pragma unroll
            for (int kt = 0; kt < 4; ++kt) {
                uint2 b = wf1[(kt * NG + gg) * 32 + lane];
                uint2 b2 = wf1[((kt + 4) * NG + gg) * 32 + lane];
                mma16816(acc, a1[kt], b.x, b.y);
                mma16816(acb, a1[kt + 4], b2.x, b2.y);
            }
            if (npass == 2) {
#pragma unroll
                for (int kt = 0; kt < 4; ++kt) {
                    uint2 b = wf2[(kt * NG + gg) * 32 + lane];
                    uint2 b2 = wf2[((kt + 4) * NG + gg) * 32 + lane];
                    mma16816(acc, a2[kt], b.x, b.y);
                    mma16816(acb, a2[kt + 4], b2.x, b2.y);
                }
            }
#pragma unroll
            for (int i = 0; i < 4; ++i) acc[i] += acb[i];
            int c0l = gg * 8 + 2 * q;
            int c0 = cbase + c0l;
            float b0 = 0.f, b1 = 0.f;
            if (bias) { b0 = bsm[c0l]; b1 = bsm[c0l + 1]; }
            float o0 = acc[0] + b0, o1 = acc[1] + b1, o2 = acc[2] + b0, o3 = acc[3] + b1;
            if (relu) {
                o0 = fmaxf(o0, 0.f); o1 = fmaxf(o1, 0.f);
                o2 = fmaxf(o2, 0.f); o3 = fmaxf(o3, 0.f);
            }
            int gr1 = gr0b + 8;
            if (obf16) {
                unsigned w0 = bf16u(o0) | (bf16u(o1) << 16);
                unsigned w1 = bf16u(o2) | (bf16u(o3) << 16);
                if (gr0b < M) *(unsigned*)((__nv_bfloat16*)out + (size_t)gr0b * N + c0) = w0;
                if (gr1  < M) *(unsigned*)((__nv_bfloat16*)out + (size_t)gr1  * N + c0) = w1;
            } else {
                if (gr0b < M) *(float2*)((float*)out + (size_t)gr0b * N + c0) = make_float2(o0, o1);
                if (gr1  < M) *(float2*)((float*)out + (size_t)gr1  * N + c0) = make_float2(o2, o3);
            }
        }
        __syncthreads();
    }
}

// ------- mma.sync LSTM: 4-warp groups, 4 groups/CTA, 4 MMA chains -------
#define LGROUPS 4
#define HSTRIDE 136
#define SM_WF    0
#define SM_BIAS  131072
#define SM_HSTG  133120
#define SM_NID   (SM_HSTG + 34816)
#define SM_USM   (SM_NID + 256)
#define SM_TOTAL (SM_USM + 4096)

__global__ __launch_bounds__(512, 1)
void lstm_mma(const int* __restrict__ nbr) {
    extern __shared__ char smr[];
    uint4*  wf  = (uint4*)(smr + SM_WF);
    float4* bsm = (float4*)(smr + SM_BIAS);
    __nv_bfloat16* hstg = (__nv_bfloat16*)(smr + SM_HSTG);
    int* nidA = (int*)(smr + SM_NID);
    int* usmA = (int*)(smr + SM_USM);

    int tid = threadIdx.x, wid = tid >> 5, lane = tid & 31;
    for (int i = tid; i < 256 * 32; i += 512) wf[i] = g_Wfrag4[i];
    if (tid < HID) bsm[tid] = g_biasF[tid];
    __syncthreads();

    int grp = wid >> 2, chunk = wid & 3;
    __nv_bfloat16* hs0 = hstg + grp * 2 * 16 * HSTRIDE;
    __nv_bfloat16* hs1 = hs0 + 16 * HSTRIDE;
    int* mynid = nidA + grp * 16;
    int* usm   = usmA + grp * 16 * MAXD;
    int r0 = lane >> 2, q = lane & 3;
    int barid = grp + 1;
    int nb = g_nbatch;
    const unsigned* PB = (const unsigned*)g_Pb;

    for (int b = blockIdx.x * LGROUPS + grp; b < nb; b += gridDim.x * LGROUPS) {
        asm volatile("bar.sync %0, %1;" :: "r"(barid), "r"(128) : "memory");
        int start = g_batch_start[b];
        int info  = g_batch_info[b];
        int dmax = info >> 8, cnt = info & 255;
        if (chunk == 0 && lane < 16) {
            int nid = g_order[start + min(lane, cnt - 1)];
            mynid[lane] = nid;
            const int4* src = (const int4*)(nbr + nid * MAXD);
            int4* dst = (int4*)(usm + lane * MAXD);
            dst[0] = src[0]; dst[1] = src[1]; dst[2] = src[2]; dst[3] = src[3];
        }
        asm volatile("bar.sync %0, %1;" :: "r"(barid), "r"(128) : "memory");

        float cst[16];
#pragma unroll
        for (int i = 0; i < 16; ++i) cst[i] = 0.f;

        unsigned pnl[16];
        {
            const unsigned* L = PB + (size_t)usm[r0 * MAXD] * 256;
#pragma unroll
            for (int nt = 0; nt < 16; ++nt) pnl[nt] = L[chunk * 64 + nt * 4 + q];
        }

        for (int t = 0; t < dmax; ++t) {
            asm volatile("bar.sync %0, %1;" :: "r"(barid), "r"(128) : "memory");
            const __nv_bfloat16* hsR = (t & 1) ? hs0 : hs1;
            __nv_bfloat16*       hsW = (t & 1) ? hs1 : hs0;

            unsigned a[8][4];
            if (t > 0) {
#pragma unroll
                for (int kt = 0; kt < 8; ++kt) {
                    const __nv_bfloat16* hb = hsR + kt * 16 + q * 2;
                    a[kt][0] = *(const unsigned*)(hb + r0 * HSTRIDE);
                    a[kt][1] = *(const unsigned*)(hb + (r0 + 8) * HSTRIDE);
                    a[kt][2] = *(const unsigned*)(hb + r0 * HSTRIDE + 8);
                    a[kt][3] = *(const unsigned*)(hb + (r0 + 8) * HSTRIDE + 8);
                }
            }
            unsigned pcl[16];
#pragma unroll
            for (int nt = 0; nt < 16; ++nt) pcl[nt] = pnl[nt];
            unsigned pch[16];
            {
                const unsigned* H = PB + (size_t)usm[(r0 + 8) * MAXD + t] * 256;
#pragma unroll
                for (int nt = 0; nt < 16; ++nt) pch[nt] = H[chunk * 64 + nt * 4 + q];
            }
            if (t + 1 < dmax) {
                const unsigned* L = PB + (size_t)usm[r0 * MAXD + t + 1] * 256;
#pragma unroll
                for (int nt = 0; nt < 16; ++nt) pnl[nt] = L[chunk * 64 + nt * 4 + q];
            }

            bool last = (t == dmax - 1);
#pragma unroll
            for (int p = 0; p < 8; ++p) {
                float aE[4] = {0.f, 0.f, 0.f, 0.f};
                float aO[4] = {0.f, 0.f, 0.f, 0.f};
                float aE2[4] = {0.f, 0.f, 0.f, 0.f};
                float aO2[4] = {0.f, 0.f, 0.f, 0.f};
                if (t > 0) {
#pragma unroll
                    for (int kt = 0; kt < 4; ++kt) {
                        uint4 b0 = wf[((kt << 5) | (chunk << 3) | p) * 32 + lane];
                        uint4 b1 = wf[(((kt + 4) << 5) | (chunk << 3) | p) * 32 + lane];
                        mma16816(aE,  a[kt],     b0.x, b0.y);
                        mma16816(aO,  a[kt],     b0.z, b0.w);
                        mma16816(aE2, a[kt + 4], b1.x, b1.y);
                        mma16816(aO2, a[kt + 4], b1.z, b1.w);
                    }
#pragma unroll
                    for (int i = 0; i < 4; ++i) { aE[i] += aE2[i]; aO[i] += aO2[i]; }
                }
                int J = chunk * 32 + p * 4 + q;
                float4 bs = bsm[J];
                {
                    float gi = aE[0] + blo(pcl[2 * p])     + bs.x;
                    float gf = aE[1] + bhi(pcl[2 * p])     + bs.y;
                    float gg = aO[0] + blo(pcl[2 * p + 1]) + bs.z;
                    float go = aO[1] + bhi(pcl[2 * p + 1]) + bs.w;
                    float cn = sigt(gf) * cst[2 * p] + sigt(gi) * tanhap(gg);
                    cst[2 * p] = cn;
                    float h = sigt(go) * tanhap(cn);
                    if (!last) hsW[r0 * HSTRIDE + J] = __float2bfloat16(h);
                    else if (r0 < cnt) g_hTb[(size_t)mynid[r0] * HID + J] = __float2bfloat16(h);
                }
                {
                    float gi = aE[2] + blo(pch[2 * p])     + bs.x;
                    float gf = aE[3] + bhi(pch[2 * p])     + bs.y;
                    float gg = aO[2] + blo(pch[2 * p + 1]) + bs.z;
                    float go = aO[3] + bhi(pch[2 * p + 1]) + bs.w;
                    float cn = sigt(gf) * cst[2 * p + 1] + sigt(gi) * tanhap(gg);
                    cst[2 * p + 1] = cn;
                    float h = sigt(go) * tanhap(cn);
                    if (!last) hsW[(r0 + 8) * HSTRIDE + J] = __float2bfloat16(h);
                    else if (r0 + 8 < cnt) g_hTb[(size_t)mynid[r0 + 8] * HID + J] = __float2bfloat16(h);
                }
            }
        }
    }
}

// ---------------- GraphConv aggregate (bf16 in/out) ----------------
__global__ void agg_kernel(const int* __restrict__ nbr, const int* __restrict__ deg) {
    int wid  = (blockIdx.x * blockDim.x + threadIdx.x) >> 5;
    int lane = threadIdx.x & 31;
    if (wid >= NNODES) return;
    int d = deg[wid];
    const int* nb = nbr + wid * MAXD;
    float a0 = 0.f, a1 = 0.f, a2 = 0.f, a3 = 0.f;
    for (int t = 0; t < d; ++t) {
        int u = nb[t];
        float nu = rsqrtf((float)max(deg[u], 1));
        uint2 v = *(const uint2*)(g_h1b + (size_t)u * 128 + lane * 4);
        a0 = fmaf(blo(v.x), nu, a0); a1 = fmaf(bhi(v.x), nu, a1);
        a2 = fmaf(blo(v.y), nu, a2); a3 = fmaf(bhi(v.y), nu, a3);
    }
    float nn = rsqrtf((float)max(d, 1));
    uint2 o;
    o.x = bf16u(a0 * nn) | (bf16u(a1 * nn) << 16);
    o.y = bf16u(a2 * nn) | (bf16u(a3 * nn) << 16);
    *(uint2*)(g_aggB + (size_t)wid * 128 + lane * 4) = o;
}

// ---------------- GRU (fp32, exact) ----------------
__global__ void gru_kernel(const float* __restrict__ bih, const float* __restrict__ bhh) {
    extern __shared__ char sm[];
    float4* Wt   = (float4*)sm;
    float*  hrow = (float*)(sm + 65536);
    int tid = threadIdx.x;
    for (int i = tid; i < HID * GRUH; i += blockDim.x) Wt[i] = g_Wt3[i];
    __syncthreads();

    int w = tid >> 5, lane = tid & 31;
    float br = bih[lane], bz = bih[32 + lane], bn = bih[64 + lane];
    float cr = bhh[lane], cz = bhh[32 + lane], cnb = bhh[64 + lane];
    float* hr = hrow + w * 128;
    int nwarp = gridDim.x * 8;
    for (int node = blockIdx.x * 8 + w; node < NNODES; node += nwarp) {
        const float* h2 = g_h2 + (size_t)node * 128;
        *(float4*)(hr + lane * 4) = *(const float4*)(h2 + lane * 4);
        __syncwarp();
        float ar = 0.f, az = 0.f, an = 0.f;
#pragma unroll 8
        for (int k = 0; k < 128; ++k) {
            float hk = hr[k];
            float4 wv = Wt[k * 32 + lane];
            ar = fmaf(hk, wv.x, ar);
            az = fmaf(hk, wv.y, az);
            an = fmaf(hk, wv.z, an);
        }
        __syncwarp();
        float r   = sigf(ar + br + cr);
        float z   = sigf(az + bz + cz);
        float nst = tanh_(an + bn + r * cnb);
        g_o32[(size_t)node * 32 + lane] = (1.f - z) * nst;
    }
}

// ---------------- mean pool (two-pass) + classifier ----------------
__global__ void pool1(const int* __restrict__ gid) {
    __shared__ float s[8][32];
    __shared__ int   scnt[8];
    int g = blockIdx.x, part = blockIdx.y;
    int tid = threadIdx.x, lane = tid & 31, slot = tid >> 5;
    int base = part * (NNODES / 4), end = base + NNODES / 4;
    float acc = 0.f;
    int cnt = 0;
    for (int i = base + slot; i < end; i += 8) {
        if (gid[i] == g) {
            acc += g_o32[(size_t)i * 32 + lane];
            cnt++;
        }
    }
    s[slot][lane] = acc;
    if (lane == 0) scnt[slot] = cnt;
    __syncthreads();
    if (tid < 32) {
        float sum = 0.f; int tot = 0;
#pragma unroll
        for (int j = 0; j < 8; ++j) { sum += s[j][tid]; tot += scnt[j]; }
        g_pp[g][part][tid] = sum;
        if (tid == 0) g_pc[g][part] = tot;
    }
}

__global__ void pool2(const float* __restrict__ Wc, const float* __restrict__ bc,
                      float* __restrict__ out) {
    __shared__ float hg[32];
    int g = blockIdx.x, tid = threadIdx.x;
    float sum = g_pp[g][0][tid] + g_pp[g][1][tid] + g_pp[g][2][tid] + g_pp[g][3][tid];
    int tot = g_pc[g][0] + g_pc[g][1] + g_pc[g][2] + g_pc[g][3];
    hg[tid] = sum / (float)tot;
    __syncwarp();
    if (tid < NCLS) {
        float o = bc[tid];
#pragma unroll
        for (int k = 0; k < 32; ++k) o = fmaf(hg[k], Wc[k * NCLS + tid], o);
        out[g * NCLS + tid] = o;
    }
}

// ---------------- launch ----------------
extern "C" void kernel_launch(void* const* d_in, const int* in_sizes, int n_in,
                              void* d_out, int out_size) {
    const float* feature = (const float*)d_in[0];
    const int*   nbr     = (const int*)  d_in[1];
    const int*   deg     = (const int*)  d_in[2];
    const int*   gid     = (const int*)  d_in[3];
    const float* lWih    = (const float*)d_in[4];
    const float* lWhh    = (const float*)d_in[5];
    const float* lbih    = (const float*)d_in[6];
    const float* lbhh    = (const float*)d_in[7];
    const float* Wself   = (const float*)d_in[8];
    const float* Wneigh  = (const float*)d_in[9];
    const float* bsage   = (const float*)d_in[10];
    const float* Wgc     = (const float*)d_in[11];
    const float* bgc     = (const float*)d_in[12];
    const float* Wgru    = (const float*)d_in[13];
    const float* bihg    = (const float*)d_in[14];
    const float* bhhg    = (const float*)d_in[15];
    const float* Wcls    = (const float*)d_in[16];
    const float* bcls    = (const float*)d_in[17];
    float* out = (float*)d_out;

    const int smP = 65536 + 8704 + 1024;   // P split (NG=32)
    const int smS = 65536 + 17408 + 1024;  // SAGE 2-pass
    const int smG = 32768 + 8704 + 1024;   // GC

    cudaFuncSetAttribute(hgemm, cudaFuncAttributeMaxDynamicSharedMemorySize, 90112);
    cudaFuncSetAttribute(lstm_mma, cudaFuncAttributeMaxDynamicSharedMemorySize, SM_TOTAL);
    cudaFuncSetAttribute(gru_kernel, cudaFuncAttributeMaxDynamicSharedMemorySize, 69632 + 256);

    void *pPb, *pFeatB, *pHtb, *pH1b, *pAggB, *pH2;
    void *pWfP, *pWfSelf, *pWfNeigh, *pWfGc;
    cudaGetSymbolAddress(&pPb,     g_Pb);
    cudaGetSymbolAddress(&pFeatB,  g_featB);
    cudaGetSymbolAddress(&pHtb,    g_hTb);
    cudaGetSymbolAddress(&pH1b,    g_h1b);
    cudaGetSymbolAddress(&pAggB,   g_aggB);
    cudaGetSymbolAddress(&pH2,     g_h2);
    cudaGetSymbolAddress(&pWfP,    g_WfP);
    cudaGetSymbolAddress(&pWfSelf, g_WfSelf);
    cudaGetSymbolAddress(&pWfNeigh,g_WfNeigh);
    cudaGetSymbolAddress(&pWfGc,   g_WfGc);

    prep_kernel<<<256, 256>>>(lWih, lWhh, lbih, lbhh, Wself, Wneigh, Wgc, Wgru);
    f2b<<<(NNODES * 128 / 4 + 255) / 256, 256>>>(feature, (__nv_bfloat16*)pFeatB, NNODES * 128 / 4);
    // P = featB @ WihT(perm) -> bf16 [N,512], column-split x2 (fixed weight gather)
    hgemm<<<304, 256, smP>>>((const __nv_bfloat16*)pFeatB, nullptr,
                             (const uint2*)pWfP, nullptr, nullptr, pPb,
                             NNODES, 512, 0, 1, 2);
    k_bucket<<<1, 512>>>(deg);
    lstm_mma<<<152, 512, SM_TOTAL>>>(nbr);
    // h1 = relu(featB@Wself + hTb@Wneigh + b_sage) -> bf16
    hgemm<<<304, 256, smS>>>((const __nv_bfloat16*)pFeatB, (const __nv_bfloat16*)pHtb,
                             (const uint2*)pWfSelf, (const uint2*)pWfNeigh, bsage, pH1b,
                             NNODES, 128, 1, 1, 1);
    agg_kernel<<<(NNODES * 32 + 255) / 256, 256>>>(nbr, deg);
    // h2 = relu(aggB @ Wgc + b_gc) -> fp32 (exact GRU path)
    hgemm<<<304, 256, smG>>>((const __nv_bfloat16*)pAggB, nullptr,
                             (const uint2*)pWfGc, nullptr, bgc, pH2,
                             NNODES, 128, 1, 0, 1);
    gru_kernel<<<304, 256, 69632 + 256>>>(bihg, bhhg);
    pool1<<<dim3(NGRAPH, 4), 256>>>(gid);
    pool2<<<NGRAPH, 32>>>(Wcls, bcls, out);
}

// round 13
// speedup vs baseline: 2.2465x; 1.2694x over previous
#include <cuda_runtime.h>
#include <cuda_bf16.h>
#include <cstdint>

#define NNODES 50000
#define HID    128
#define MAXD   16
#define NGRAPH 50
#define NCLS   10
#define GRUH   32
#define MAXB   3400

// ---------------- scratch ----------------
__device__ __nv_bfloat16 g_Pb [(size_t)NNODES * 512];
__device__ __nv_bfloat16 g_featB[(size_t)NNODES * HID];
__device__ __nv_bfloat16 g_hTb [(size_t)NNODES * HID];
__device__ __nv_bfloat16 g_h1b [(size_t)NNODES * HID];
__device__ __nv_bfloat16 g_aggB[(size_t)NNODES * HID];
__device__ __nv_bfloat16 g_h2b [(size_t)NNODES * HID];
__device__ float g_gh [(size_t)NNODES * 96];
__device__ float g_o32[(size_t)NNODES * GRUH];
__device__ uint2 g_WfP[16384];               // Wih fragments (N=512, permuted cols, kt-major)
__device__ uint2 g_WfSelf[4096];
__device__ uint2 g_WfNeigh[4096];
__device__ uint2 g_WfGc[4096];
__device__ uint2 g_WfGru[3072];              // N=96
__device__ uint4 g_Wfrag4[256 * 32];         // lstm Whh fragments, E/O fused
__device__ float4 g_biasF[HID];              // (bi,bf,bg,bo)
__device__ float g_pp[NGRAPH][4][32];
__device__ int   g_pc[NGRAPH][4];
// degree bucketing
__device__ int g_order[NNODES];
__device__ int g_bincnt[16];
__device__ int g_binoff[16];
__device__ int g_batch_start[MAXB];
__device__ int g_batch_info[MAXB];
__device__ int g_nbatch;

// ---------------- helpers ----------------
__device__ __forceinline__ float sigf(float x) {
    x = fminf(fmaxf(x, -30.f), 30.f);
    return __fdividef(1.f, 1.f + __expf(-x));
}
__device__ __forceinline__ float tanh_(float x) {
    x = fminf(fmaxf(x, -15.f), 15.f);
    float e = __expf(-2.f * x);
    return __fdividef(1.f - e, 1.f + e);
}
__device__ __forceinline__ float tanhap(float x) {
    float y; asm("tanh.approx.f32 %0, %1;" : "=f"(y) : "f"(x)); return y;
}
__device__ __forceinline__ float sigt(float x) { return fmaf(tanhap(x * 0.5f), 0.5f, 0.5f); }
__device__ __forceinline__ unsigned bf16u(float x) {
    __nv_bfloat16 b = __float2bfloat16(x);
    return (unsigned)*reinterpret_cast<unsigned short*>(&b);
}
__device__ __forceinline__ float blo(unsigned v) { return __uint_as_float(v << 16); }
__device__ __forceinline__ float bhi(unsigned v) { return __uint_as_float(v & 0xFFFF0000u); }

__host__ __device__ __forceinline__ int phys2row(int p) {
    int pb = p >> 4, rem = p & 15;
    int gamma, aa;
    if (rem < 8) { aa = rem >> 1; gamma = (rem & 1) ? 1 : 0; }
    else         { aa = (rem - 8) >> 1; gamma = (rem & 1) ? 3 : 2; }
    return gamma * HID + pb * 4 + aa;
}

__device__ __forceinline__ void mma16816(float* d, const unsigned* a, unsigned b0, unsigned b1) {
    asm volatile(
        "mma.sync.aligned.m16n8k16.row.col.f32.bf16.bf16.f32 "
        "{%0,%1,%2,%3}, {%4,%5,%6,%7}, {%8,%9}, {%0,%1,%2,%3};"
        : "+f"(d[0]), "+f"(d[1]), "+f"(d[2]), "+f"(d[3])
        : "r"(a[0]), "r"(a[1]), "r"(a[2]), "r"(a[3]), "r"(b0), "r"(b1));
}

// ---------------- prep: all weight packing (+ bincnt reset) ----------------
__global__ void prep_kernel(const float* __restrict__ Wih,
                            const float* __restrict__ Whh,
                            const float* __restrict__ bih,
                            const float* __restrict__ bhh,
                            const float* __restrict__ Wself,
                            const float* __restrict__ Wneigh,
                            const float* __restrict__ Wgc,
                            const float* __restrict__ Wgru) {
    int idx = blockIdx.x * blockDim.x + threadIdx.x;
    if (idx < 16) g_bincnt[idx] = 0;
    if (idx < 16384) {
        int l = idx & 31, t = idx >> 5;
        int kt = t >> 6, g = t & 63;
        int n = g * 8 + (l >> 2);
        int k0 = kt * 16 + (l & 3) * 2;
        int r = phys2row(n) * HID;
        uint2 v;
        v.x = bf16u(Wih[r + k0])     | (bf16u(Wih[r + k0 + 1]) << 16);
        v.y = bf16u(Wih[r + k0 + 8]) | (bf16u(Wih[r + k0 + 9]) << 16);
        g_WfP[idx] = v;
    }
    if (idx < 4096) {
        int l = idx & 31, t = idx >> 5;
        int kt = t >> 4, g = t & 15;
        int n = g * 8 + (l >> 2);
        int k0 = kt * 16 + (l & 3) * 2;
        uint2 v;
        v.x = bf16u(Wself[k0 * HID + n])       | (bf16u(Wself[(k0 + 1) * HID + n]) << 16);
        v.y = bf16u(Wself[(k0 + 8) * HID + n]) | (bf16u(Wself[(k0 + 9) * HID + n]) << 16);
        g_WfSelf[idx] = v;
        v.x = bf16u(Wneigh[k0 * HID + n])       | (bf16u(Wneigh[(k0 + 1) * HID + n]) << 16);
        v.y = bf16u(Wneigh[(k0 + 8) * HID + n]) | (bf16u(Wneigh[(k0 + 9) * HID + n]) << 16);
        g_WfNeigh[idx] = v;
        v.x = bf16u(Wgc[k0 * HID + n])       | (bf16u(Wgc[(k0 + 1) * HID + n]) << 16);
        v.y = bf16u(Wgc[(k0 + 8) * HID + n]) | (bf16u(Wgc[(k0 + 9) * HID + n]) << 16);
        g_WfGc[idx] = v;
    }
    if (idx < 3072) {          // GRU fragments: Wt[k][n] = Wgru[n*HID+k], n = gate*32+l
        int l = idx & 31, t = idx >> 5;
        int kt = t / 12, gg = t % 12;
        int n = gg * 8 + (l >> 2);
        int k0 = kt * 16 + (l & 3) * 2;
        uint2 v;
        v.x = bf16u(Wgru[n * HID + k0])     | (bf16u(Wgru[n * HID + k0 + 1]) << 16);
        v.y = bf16u(Wgru[n * HID + k0 + 8]) | (bf16u(Wgru[n * HID + k0 + 9]) << 16);
        g_WfGru[idx] = v;
    }
    if (idx < 512 * 32) {
        int t_id = idx >> 5, lane = idx & 31;
        int kt = t_id >> 6, ntg = t_id & 63;
        int p = ntg * 8 + (lane >> 2);
        int wrow = phys2row(p);
        int k0 = kt * 16 + (lane & 3) * 2;
        const float* wr = Whh + (size_t)wrow * HID;
        uint2 v;
        v.x = bf16u(wr[k0])     | (bf16u(wr[k0 + 1]) << 16);
        v.y = bf16u(wr[k0 + 8]) | (bf16u(wr[k0 + 9]) << 16);
        int chunk = ntg >> 4, nt = ntg & 15;
        int pp = nt >> 1, isO = nt & 1;
        int dst = (((kt << 5) | (chunk << 3) | pp) * 32 + lane) * 2 + isO;
        ((uint2*)g_Wfrag4)[dst] = v;
    }
    if (idx < HID) {
        g_biasF[idx] = make_float4(bih[idx] + bhh[idx],
                                   bih[HID + idx] + bhh[HID + idx],
                                   bih[2 * HID + idx] + bhh[2 * HID + idx],
                                   bih[3 * HID + idx] + bhh[3 * HID + idx]);
    }
}

// ---------------- feature -> bf16 ----------------
__global__ void f2b(const float* __restrict__ src, __nv_bfloat16* __restrict__ dst, int n4) {
    int i = blockIdx.x * blockDim.x + threadIdx.x;
    if (i < n4) {
        float4 v = ((const float4*)src)[i];
        uint2 o;
        o.x = bf16u(v.x) | (bf16u(v.y) << 16);
        o.y = bf16u(v.z) | (bf16u(v.w) << 16);
        ((uint2*)dst)[i] = o;
    }
}

// -------- multi-block bucketing: hist -> offsets/batches -> scatter --------
__global__ void k_hist(const int* __restrict__ deg) {
    __shared__ int h[16];
    if (threadIdx.x < 16) h[threadIdx.x] = 0;
    __syncthreads();
    for (int i = blockIdx.x * blockDim.x + threadIdx.x; i < NNODES; i += gridDim.x * blockDim.x)
        atomicAdd(&h[deg[i] - 1], 1);
    __syncthreads();
    if (threadIdx.x < 16) atomicAdd(&g_bincnt[threadIdx.x], h[threadIdx.x]);
}

__global__ void k_offsets() {
    __shared__ int btot[16], binbase[16], bOffD[16];
    __shared__ int nbatch_s;
    int tid = threadIdx.x;
    if (tid == 0) {
        int off = 0;
        for (int b = 0; b < 16; ++b) {
            btot[b] = g_bincnt[b];
            binbase[b] = off;
            g_binoff[b] = off;
            off += btot[b];
        }
        int bo = 0;
        for (int b = 15; b >= 0; --b) { bOffD[b] = bo; bo += (btot[b] + 15) >> 4; }
        nbatch_s = bo;
        g_nbatch = bo;
    }
    __syncthreads();
    int nb = nbatch_s;
    for (int bi = tid; bi < nb; bi += blockDim.x) {
        int bin = 0;
#pragma unroll
        for (int b = 15; b >= 0; --b) {
            int nbb = (btot[b] + 15) >> 4;
            if (bi >= bOffD[b] && bi < bOffD[b] + nbb) { bin = b; break; }
        }
        int j = (bi - bOffD[bin]) * 16;
        g_batch_start[bi] = binbase[bin] + j;
        g_batch_info[bi]  = ((bin + 1) << 8) | min(16, btot[bin] - j);
    }
}

__global__ void k_scatter(const int* __restrict__ deg) {
    __shared__ int scnt[16], sbase[16], scur[16];
    int t = threadIdx.x;
    if (t < 16) { scnt[t] = 0; scur[t] = 0; }
    __syncthreads();
    int i = blockIdx.x * 512 + t;
    int d = -1;
    if (i < NNODES) { d = deg[i] - 1; atomicAdd(&scnt[d], 1); }
    __syncthreads();
    if (t < 16 && scnt[t] > 0) sbase[t] = atomicAdd(&g_binoff[t], scnt[t]);
    __syncthreads();
    if (i < NNODES) {
        int pos = sbase[d] + atomicAdd(&scur[d], 1);
        g_order[pos] = i;
    }
}

// ---------------- bf16 HMMA GEMM, K=128, dual accumulation chains ----------------
#define AS 136

__global__ __launch_bounds__(256, 2)
void hgemm(const __nv_bfloat16* __restrict__ A1, const __nv_bfloat16* __restrict__ A2,
           const uint2* __restrict__ W1, const uint2* __restrict__ W2,
           const float* __restrict__ bias, void* __restrict__ out,
           int M, int N, int relu, int obf16, int splits) {
    extern __shared__ char sm[];
    int Nc = N / splits;
    int NG = Nc >> 3;
    int NGfull = N >> 3;
    int nw = 8 * NG * 32;
    int sp = blockIdx.x & (splits - 1);
    int cbase = sp * Nc;
    int nCTA = gridDim.x >> (splits - 1);
    int npass = (A2 != nullptr) ? 2 : 1;
    uint2* wf1 = (uint2*)sm;
    uint2* wf2 = wf1 + nw;
    unsigned short* ast = (unsigned short*)(wf1 + (size_t)npass * nw);
    float* bsm = (float*)(ast + npass * 32 * AS);

    int tid = threadIdx.x, wid = tid >> 5, lane = tid & 31;
    {
        for (int i = tid; i < nw; i += 256) {
            int t2 = i >> 5, li = i & 31;
            int kt = t2 / NG, gg = t2 - kt * NG;
            int src = (kt * NGfull + sp * NG + gg) * 32 + li;
            wf1[i] = W1[src];
            if (npass == 2) wf2[i] = W2[src];
        }
    }
    if (bias) for (int i = tid; i < Nc; i += 256) bsm[i] = bias[cbase + i];

    int rh = wid & 1, cc = wid >> 1;
    int gpw = NG >> 2;
    int r0 = lane >> 2, q = lane & 3;
    int nbat = (M + 31) >> 5;
    int lrow = tid >> 3, lch = tid & 7;

    uint4 pf[2][2];
    int bi = blockIdx.x >> (splits - 1);
    if (bi < nbat) {
        int gr = min(bi * 32 + lrow, M - 1);
        const uint4* s = (const uint4*)(A1 + (size_t)gr * 128 + lch * 16);
        pf[0][0] = s[0]; pf[0][1] = s[1];
        if (npass == 2) {
            const uint4* s2 = (const uint4*)(A2 + (size_t)gr * 128 + lch * 16);
            pf[1][0] = s2[0]; pf[1][1] = s2[1];
        }
    }
    __syncthreads();

    for (; bi < nbat; bi += nCTA) {
        {
            uint4* d = (uint4*)(ast + lrow * AS + lch * 16);
            d[0] = pf[0][0]; d[1] = pf[0][1];
            if (npass == 2) {
                uint4* d2 = (uint4*)(ast + 32 * AS + lrow * AS + lch * 16);
                d2[0] = pf[1][0]; d2[1] = pf[1][1];
            }
        }
        __syncthreads();
        int bn = bi + nCTA;
        if (bn < nbat) {
            int gr = min(bn * 32 + lrow, M - 1);
            const uint4* s = (const uint4*)(A1 + (size_t)gr * 128 + lch * 16);
            pf[0][0] = s[0]; pf[0][1] = s[1];
            if (npass == 2) {
                const uint4* s2 = (const uint4*)(A2 + (size_t)gr * 128 + lch * 16);
                pf[1][0] = s2[0]; pf[1][1] = s2[1];
            }
        }
        unsigned a1[8][4], a2[8][4];
        {
            const unsigned short* base = ast + (rh * 16) * AS;
#pragma unroll
            for (int kt = 0; kt < 8; ++kt) {
                const unsigned short* hb = base + kt * 16 + q * 2;
                a1[kt][0] = *(const unsigned*)(hb + r0 * AS);
                a1[kt][1] = *(const unsigned*)(hb + (r0 + 8) * AS);
                a1[kt][2] = *(const unsigned*)(hb + r0 * AS + 8);
                a1[kt][3] = *(const unsigned*)(hb + (r0 + 8) * AS + 8);
            }
            if (npass == 2) {
                const unsigned short* b2 = base + 32 * AS;
#pragma unroll
                for (int kt = 0; kt < 8; ++kt) {
                    const unsigned short* hb = b2 + kt * 16 + q * 2;
                    a2[kt][0] = *(const unsigned*)(hb + r0 * AS);
                    a2[kt][1] = *(const unsigned*)(hb + (r0 + 8) * AS);
                    a2[kt][2] = *(const unsigned*)(hb + r0 * AS + 8);
                    a2[kt][3] = *(const unsigned*)(hb + (r0 + 8) * AS + 8);
                }
            }
        }
        int gr0b = bi * 32 + rh * 16 + r0;
        for (int g = 0; g < gpw; ++g) {
            int gg = cc * gpw + g;
            float acc[4] = {0.f, 0.f, 0.f, 0.f};
            float acb[4] = {0.f, 0.f, 0.f, 0.f};
#pragma unroll
            for (int kt = 0; kt < 4; ++kt) {
                uint2 b = wf1[(kt * NG + gg) * 32 + lane];
                uint2 b2 = wf1[((kt + 4) * NG + gg) * 32 + lane];
                mma16816(acc, a1[kt], b.x, b.y);
                mma16816(acb, a1[kt + 4], b2.x, b2.y);
            }
            if (npass == 2) {
#pragma unroll
                for (int kt = 0; kt < 4; ++kt) {
                    uint2 b = wf2[(kt * NG + gg) * 32 + lane];
                    uint2 b2 = wf2[((kt + 4) * NG + gg) * 32 + lane];
                    mma16816(acc, a2[kt], b.x, b.y);
                    mma16816(acb, a2[kt + 4], b2.x, b2.y);
                }
            }
#pragma unroll
            for (int i = 0; i < 4; ++i) acc[i] += acb[i];
            int c0l = gg * 8 + 2 * q;
            int c0 = cbase + c0l;
            float b0 = 0.f, b1 = 0.f;
            if (bias) { b0 = bsm[c0l]; b1 = bsm[c0l + 1]; }
            float o0 = acc[0] + b0, o1 = acc[1] + b1, o2 = acc[2] + b0, o3 = acc[3] + b1;
            if (relu) {
                o0 = fmaxf(o0, 0.f); o1 = fmaxf(o1, 0.f);
                o2 = fmaxf(o2, 0.f); o3 = fmaxf(o3, 0.f);
            }
            int gr1 = gr0b + 8;
            if (obf16) {
                unsigned w0 = bf16u(o0) | (bf16u(o1) << 16);
                unsigned w1 = bf16u(o2) | (bf16u(o3) << 16);
                if (gr0b < M) *(unsigned*)((__nv_bfloat16*)out + (size_t)gr0b * N + c0) = w0;
                if (gr1  < M) *(unsigned*)((__nv_bfloat16*)out + (size_t)gr1  * N + c0) = w1;
            } else {
                if (gr0b < M) *(float2*)((float*)out + (size_t)gr0b * N + c0) = make_float2(o0, o1);
                if (gr1  < M) *(float2*)((float*)out + (size_t)gr1  * N + c0) = make_float2(o2, o3);
            }
        }
        __syncthreads();
    }
}

// ------- mma.sync LSTM: 4-warp groups, 4 groups/CTA, 4 MMA chains -------
#define LGROUPS 4
#define HSTRIDE 136
#define SM_WF    0
#define SM_BIAS  131072
#define SM_HSTG  133120
#define SM_NID   (SM_HSTG + 34816)
#define SM_USM   (SM_NID + 256)
#define SM_TOTAL (SM_USM + 4096)

__global__ __launch_bounds__(512, 1)
void lstm_mma(const int* __restrict__ nbr) {
    extern __shared__ char smr[];
    uint4*  wf  = (uint4*)(smr + SM_WF);
    float4* bsm = (float4*)(smr + SM_BIAS);
    __nv_bfloat16* hstg = (__nv_bfloat16*)(smr + SM_HSTG);
    int* nidA = (int*)(smr + SM_NID);
    int* usmA = (int*)(smr + SM_USM);

    int tid = threadIdx.x, wid = tid >> 5, lane = tid & 31;
    for (int i = tid; i < 256 * 32; i += 512) wf[i] = g_Wfrag4[i];
    if (tid < HID) bsm[tid] = g_biasF[tid];
    __syncthreads();

    int grp = wid >> 2, chunk = wid & 3;
    __nv_bfloat16* hs0 = hstg + grp * 2 * 16 * HSTRIDE;
    __nv_bfloat16* hs1 = hs0 + 16 * HSTRIDE;
    int* mynid = nidA + grp * 16;
    int* usm   = usmA + grp * 16 * MAXD;
    int r0 = lane >> 2, q = lane & 3;
    int barid = grp + 1;
    int nb = g_nbatch;
    const unsigned* PB = (const unsigned*)g_Pb;

    for (int b = blockIdx.x * LGROUPS + grp; b < nb; b += gridDim.x * LGROUPS) {
        asm volatile("bar.sync %0, %1;" :: "r"(barid), "r"(128) : "memory");
        int start = g_batch_start[b];
        int info  = g_batch_info[b];
        int dmax = info >> 8, cnt = info & 255;
        if (chunk == 0 && lane < 16) {
            int nid = g_order[start + min(lane, cnt - 1)];
            mynid[lane] = nid;
            const int4* src = (const int4*)(nbr + nid * MAXD);
            int4* dst = (int4*)(usm + lane * MAXD);
            dst[0] = src[0]; dst[1] = src[1]; dst[2] = src[2]; dst[3] = src[3];
        }
        asm volatile("bar.sync %0, %1;" :: "r"(barid), "r"(128) : "memory");

        float cst[16];
#pragma unroll
        for (int i = 0; i < 16; ++i) cst[i] = 0.f;

        unsigned pnl[16];
        {
            const unsigned* L = PB + (size_t)usm[r0 * MAXD] * 256;
#pragma unroll
            for (int nt = 0; nt < 16; ++nt) pnl[nt] = L[chunk * 64 + nt * 4 + q];
        }

        for (int t = 0; t < dmax; ++t) {
            asm volatile("bar.sync %0, %1;" :: "r"(barid), "r"(128) : "memory");
            const __nv_bfloat16* hsR = (t & 1) ? hs0 : hs1;
            __nv_bfloat16*       hsW = (t & 1) ? hs1 : hs0;

            unsigned a[8][4];
            if (t > 0) {
#pragma unroll
                for (int kt = 0; kt < 8; ++kt) {
                    const __nv_bfloat16* hb = hsR + kt * 16 + q * 2;
                    a[kt][0] = *(const unsigned*)(hb + r0 * HSTRIDE);
                    a[kt][1] = *(const unsigned*)(hb + (r0 + 8) * HSTRIDE);
                    a[kt][2] = *(const unsigned*)(hb + r0 * HSTRIDE + 8);
                    a[kt][3] = *(const unsigned*)(hb + (r0 + 8) * HSTRIDE + 8);
                }
            }
            unsigned pcl[16];
#pragma unroll
            for (int nt = 0; nt < 16; ++nt) pcl[nt] = pnl[nt];
            unsigned pch[16];
            {
                const unsigned* H = PB + (size_t)usm[(r0 + 8) * MAXD + t] * 256;
#pragma unroll
                for (int nt = 0; nt < 16; ++nt) pch[nt] = H[chunk * 64 + nt * 4 + q];
            }
            if (t + 1 < dmax) {
                const unsigned* L = PB + (size_t)usm[r0 * MAXD + t + 1] * 256;
#pragma unroll
                for (int nt = 0; nt < 16; ++nt) pnl[nt] = L[chunk * 64 + nt * 4 + q];
            }

            bool last = (t == dmax - 1);
#pragma unroll
            for (int p = 0; p < 8; ++p) {
                float aE[4] = {0.f, 0.f, 0.f, 0.f};
                float aO[4] = {0.f, 0.f, 0.f, 0.f};
                float aE2[4] = {0.f, 0.f, 0.f, 0.f};
                float aO2[4] = {0.f, 0.f, 0.f, 0.f};
                if (t > 0) {
#pragma unroll
                    for (int kt = 0; kt < 4; ++kt) {
                        uint4 b0 = wf[((kt << 5) | (chunk << 3) | p) * 32 + lane];
                        uint4 b1 = wf[(((kt + 4) << 5) | (chunk << 3) | p) * 32 + lane];
                        mma16816(aE,  a[kt],     b0.x, b0.y);
                        mma16816(aO,  a[kt],     b0.z, b0.w);
                        mma16816(aE2, a[kt + 4], b1.x, b1.y);
                        mma16816(aO2, a[kt + 4], b1.z, b1.w);
                    }
#pragma unroll
                    for (int i = 0; i < 4; ++i) { aE[i] += aE2[i]; aO[i] += aO2[i]; }
                }
                int J = chunk * 32 + p * 4 + q;
                float4 bs = bsm[J];
                {
                    float gi = aE[0] + blo(pcl[2 * p])     + bs.x;
                    float gf = aE[1] + bhi(pcl[2 * p])     + bs.y;
                    float gg = aO[0] + blo(pcl[2 * p + 1]) + bs.z;
                    float go = aO[1] + bhi(pcl[2 * p + 1]) + bs.w;
                    float cn = sigt(gf) * cst[2 * p] + sigt(gi) * tanhap(gg);
                    cst[2 * p] = cn;
                    float h = sigt(go) * tanhap(cn);
                    if (!last) hsW[r0 * HSTRIDE + J] = __float2bfloat16(h);
                    else if (r0 < cnt) g_hTb[(size_t)mynid[r0] * HID + J] = __float2bfloat16(h);
                }
                {
                    float gi = aE[2] + blo(pch[2 * p])     + bs.x;
                    float gf = aE[3] + bhi(pch[2 * p])     + bs.y;
                    float gg = aO[2] + blo(pch[2 * p + 1]) + bs.z;
                    float go = aO[3] + bhi(pch[2 * p + 1]) + bs.w;
                    float cn = sigt(gf) * cst[2 * p + 1] + sigt(gi) * tanhap(gg);
                    cst[2 * p + 1] = cn;
                    float h = sigt(go) * tanhap(cn);
                    if (!last) hsW[(r0 + 8) * HSTRIDE + J] = __float2bfloat16(h);
                    else if (r0 + 8 < cnt) g_hTb[(size_t)mynid[r0 + 8] * HID + J] = __float2bfloat16(h);
                }
            }
        }
    }
}

// ---------------- GraphConv aggregate (bf16 in/out) ----------------
__global__ void agg_kernel(const int* __restrict__ nbr, const int* __restrict__ deg) {
    int wid  = (blockIdx.x * blockDim.x + threadIdx.x) >> 5;
    int lane = threadIdx.x & 31;
    if (wid >= NNODES) return;
    int d = deg[wid];
    const int* nb = nbr + wid * MAXD;
    float a0 = 0.f, a1 = 0.f, a2 = 0.f, a3 = 0.f;
    for (int t = 0; t < d; ++t) {
        int u = nb[t];
        float nu = rsqrtf((float)max(deg[u], 1));
        uint2 v = *(const uint2*)(g_h1b + (size_t)u * 128 + lane * 4);
        a0 = fmaf(blo(v.x), nu, a0); a1 = fmaf(bhi(v.x), nu, a1);
        a2 = fmaf(blo(v.y), nu, a2); a3 = fmaf(bhi(v.y), nu, a3);
    }
    float nn = rsqrtf((float)max(d, 1));
    uint2 o;
    o.x = bf16u(a0 * nn) | (bf16u(a1 * nn) << 16);
    o.y = bf16u(a2 * nn) | (bf16u(a3 * nn) << 16);
    *(uint2*)(g_aggB + (size_t)wid * 128 + lane * 4) = o;
}

// ---------------- GRU activation (gates from hgemm) ----------------
__global__ void gruact(const float* __restrict__ bih, const float* __restrict__ bhh) {
    int i = blockIdx.x * blockDim.x + threadIdx.x;
    if (i >= NNODES * GRUH) return;
    int n = i >> 5, l = i & 31;
    const float* g = g_gh + (size_t)n * 96;
    float xr = g[l]      + bih[l];
    float xz = g[32 + l] + bih[32 + l];
    float xn = g[64 + l] + bih[64 + l];
    float r   = sigf(xr + bhh[l]);
    float z   = sigf(xz + bhh[32 + l]);
    float nst = tanh_(xn + r * bhh[64 + l]);
    g_o32[i] = (1.f - z) * nst;
}

// ---------------- mean pool (two-pass) + classifier ----------------
__global__ void pool1(const int* __restrict__ gid) {
    __shared__ float s[8][32];
    __shared__ int   scnt[8];
    int g = blockIdx.x, part = blockIdx.y;
    int tid = threadIdx.x, lane = tid & 31, slot = tid >> 5;
    int base = part * (NNODES / 4), end = base + NNODES / 4;
    float acc = 0.f;
    int cnt = 0;
    for (int i = base + slot; i < end; i += 8) {
        if (gid[i] == g) {
            acc += g_o32[(size_t)i * 32 + lane];
            cnt++;
        }
    }
    s[slot][lane] = acc;
    if (lane == 0) scnt[slot] = cnt;
    __syncthreads();
    if (tid < 32) {
        float sum = 0.f; int tot = 0;
#pragma unroll
        for (int j = 0; j < 8; ++j) { sum += s[j][tid]; tot += scnt[j]; }
        g_pp[g][part][tid] = sum;
        if (tid == 0) g_pc[g][part] = tot;
    }
}

__global__ void pool2(const float* __restrict__ Wc, const float* __restrict__ bc,
                      float* __restrict__ out) {
    __shared__ float hg[32];
    int g = blockIdx.x, tid = threadIdx.x;
    float sum = g_pp[g][0][tid] + g_pp[g][1][tid] + g_pp[g][2][tid] + g_pp[g][3][tid];
    int tot = g_pc[g][0] + g_pc[g][1] + g_pc[g][2] + g_pc[g][3];
    hg[tid] = sum / (float)tot;
    __syncwarp();
    if (tid < NCLS) {
        float o = bc[tid];
#pragma unroll
        for (int k = 0; k < 32; ++k) o = fmaf(hg[k], Wc[k * NCLS + tid], o);
        out[g * NCLS + tid] = o;
    }
}

// ---------------- launch ----------------
extern "C" void kernel_launch(void* const* d_in, const int* in_sizes, int n_in,
                              void* d_out, int out_size) {
    const float* feature = (const float*)d_in[0];
    const int*   nbr     = (const int*)  d_in[1];
    const int*   deg     = (const int*)  d_in[2];
    const int*   gid     = (const int*)  d_in[3];
    const float* lWih    = (const float*)d_in[4];
    const float* lWhh    = (const float*)d_in[5];
    const float* lbih    = (const float*)d_in[6];
    const float* lbhh    = (const float*)d_in[7];
    const float* Wself   = (const float*)d_in[8];
    const float* Wneigh  = (const float*)d_in[9];
    const float* bsage   = (const float*)d_in[10];
    const float* Wgc     = (const float*)d_in[11];
    const float* bgc     = (const float*)d_in[12];
    const float* Wgru    = (const float*)d_in[13];
    const float* bihg    = (const float*)d_in[14];
    const float* bhhg    = (const float*)d_in[15];
    const float* Wcls    = (const float*)d_in[16];
    const float* bcls    = (const float*)d_in[17];
    float* out = (float*)d_out;

    const int smP = 65536 + 8704 + 1024;   // P split (NG=32)
    const int smS = 65536 + 17408 + 1024;  // SAGE 2-pass
    const int smG = 32768 + 8704 + 1024;   // GC
    const int smR = 24576 + 8704 + 1024;   // GRU N=96

    cudaFuncSetAttribute(hgemm, cudaFuncAttributeMaxDynamicSharedMemorySize, 90112);
    cudaFuncSetAttribute(lstm_mma, cudaFuncAttributeMaxDynamicSharedMemorySize, SM_TOTAL);

    void *pPb, *pFeatB, *pHtb, *pH1b, *pAggB, *pH2b, *pGh;
    void *pWfP, *pWfSelf, *pWfNeigh, *pWfGc, *pWfGru;
    cudaGetSymbolAddress(&pPb,     g_Pb);
    cudaGetSymbolAddress(&pFeatB,  g_featB);
    cudaGetSymbolAddress(&pHtb,    g_hTb);
    cudaGetSymbolAddress(&pH1b,    g_h1b);
    cudaGetSymbolAddress(&pAggB,   g_aggB);
    cudaGetSymbolAddress(&pH2b,    g_h2b);
    cudaGetSymbolAddress(&pGh,     g_gh);
    cudaGetSymbolAddress(&pWfP,    g_WfP);
    cudaGetSymbolAddress(&pWfSelf, g_WfSelf);
    cudaGetSymbolAddress(&pWfNeigh,g_WfNeigh);
    cudaGetSymbolAddress(&pWfGc,   g_WfGc);
    cudaGetSymbolAddress(&pWfGru,  g_WfGru);

    prep_kernel<<<256, 256>>>(lWih, lWhh, lbih, lbhh, Wself, Wneigh, Wgc, Wgru);
    f2b<<<(NNODES * 128 / 4 + 255) / 256, 256>>>(feature, (__nv_bfloat16*)pFeatB, NNODES * 128 / 4);
    // P = featB @ WihT(perm) -> bf16 [N,512], column-split x2
    hgemm<<<304, 256, smP>>>((const __nv_bfloat16*)pFeatB, nullptr,
                             (const uint2*)pWfP, nullptr, nullptr, pPb,
                             NNODES, 512, 0, 1, 2);
    // multi-block bucketing
    k_hist<<<98, 512>>>(deg);
    k_offsets<<<1, 512>>>();
    k_scatter<<<98, 512>>>(deg);
    lstm_mma<<<152, 512, SM_TOTAL>>>(nbr);
    // h1 = relu(featB@Wself + hTb@Wneigh + b_sage) -> bf16
    hgemm<<<304, 256, smS>>>((const __nv_bfloat16*)pFeatB, (const __nv_bfloat16*)pHtb,
                             (const uint2*)pWfSelf, (const uint2*)pWfNeigh, bsage, pH1b,
                             NNODES, 128, 1, 1, 1);
    agg_kernel<<<(NNODES * 32 + 255) / 256, 256>>>(nbr, deg);
    // h2 = relu(aggB @ Wgc + b_gc) -> bf16
    hgemm<<<304, 256, smG>>>((const __nv_bfloat16*)pAggB, nullptr,
                             (const uint2*)pWfGc, nullptr, bgc, pH2b,
                             NNODES, 128, 1, 1, 1);
    // gh = h2b @ WgruT -> f32 [N,96]
    hgemm<<<304, 256, smR>>>((const __nv_bfloat16*)pH2b, nullptr,
                             (const uint2*)pWfGru, nullptr, nullptr, pGh,
                             NNODES, 96, 0, 0, 1);
    gruact<<<(NNODES * GRUH + 255) / 256, 256>>>(bihg, bhhg);
    pool1<<<dim3(NGRAPH, 4), 256>>>(gid);
    pool2<<<NGRAPH, 32>>>(Wcls, bcls, out);
}